// round 3
// baseline (speedup 1.0000x reference)
#include <cuda_runtime.h>
#include <cstdint>

#define N_NODES 200000
#define DIM 64
#define NQ 4096
#define GRP 64
#define E1N 262144
#define E0N 131072
#define KSEL 10

// Output layout (f32 concat): score[N], repr[N*64], pruned_edges[Q*K*8], orig_idx[Q*K]
#define OFF_REPR  (N_NODES)
#define OFF_PE    (N_NODES + N_NODES*DIM)
#define OFF_OI    (OFF_PE + NQ*KSEL*8)

// ---------------- scratch (device globals; no allocation) ----------------
__device__ float    g_M [256*256];
__device__ float    g_WqT[256*256];
__device__ float    g_B1[64*192];       // per-node transform weights: P|U|WdT
__device__ float    g_B2[64*64];        // M11^T
__device__ float    g_BL[64*64];        // W_lin^T
__device__ float    g_Bq[128*320];      // query-table weights: d|ce|v|T
__device__ float    g_QA[NQ*128];       // [qst|qrl]
__device__ float    g_QT[(size_t)NQ*320];
__device__ float    g_Qk0[NQ];
__device__ float    g_nodeT[(size_t)N_NODES*192];
__device__ float    g_quad1[E1N];
__device__ float    g_quad0[E0N];
__device__ float    g_logit[E1N];       // logits, then exp values (in place)
__device__ int      g_esrc[E1N];
__device__ int      g_edst[E1N];
__device__ unsigned g_segmax[N_NODES];
__device__ float    g_segsum[N_NODES];
__device__ int      g_has[N_NODES];
__device__ float    g_H1[(size_t)N_NODES*DIM];
__device__ float    g_H2[(size_t)N_NODES*DIM];
__device__ int      g_psrc[NQ*KSEL];
__device__ int      g_pdst[NQ*KSEL];
__device__ float    g_ptrans[NQ*KSEL];
__device__ int      g_chg[NQ*KSEL];
__device__ int      g_ncnt;

// ---------------- helpers ----------------
__device__ __forceinline__ unsigned encf(float f) {
    unsigned u = __float_as_uint(f);
    return (u & 0x80000000u) ? ~u : (u | 0x80000000u);
}
__device__ __forceinline__ float decf(unsigned u) {
    return (u & 0x80000000u) ? __uint_as_float(u & 0x7fffffffu) : __uint_as_float(~u);
}

// ---------------- init kernels ----------------
__global__ void k_init1(float* outScore) {
    int i = blockIdx.x * blockDim.x + threadIdx.x;
    if (i < N_NODES) { g_segmax[i] = 0u; g_segsum[i] = 0.f; g_has[i] = 0; outScore[i] = 0.f; }
    if (i == 0) g_ncnt = 0;
}
__global__ void k_init2() {
    int i = blockIdx.x * blockDim.x + threadIdx.x;
    if (i < N_NODES) { g_segmax[i] = 0u; g_segsum[i] = 0.f; g_has[i] = 0; }
}

__global__ void k_transQ(const float* __restrict__ Wq) {
    int id = blockIdx.x * blockDim.x + threadIdx.x;   // 65536
    int i = id >> 8, k = id & 255;
    g_WqT[i*256 + k] = Wq[k*256 + i];
}

__global__ void k_buildB(const float* __restrict__ W_lin) {
    int t = blockIdx.x * blockDim.x + threadIdx.x;
    if (t < 64*192) {
        int k = t / 192, c = t % 192;
        float v;
        if (c < 128) v = g_M[k*256 + c];                 // M00|M01
        else         v = g_M[(64 + (c-128))*256 + k];    // M10^T
        g_B1[t] = v;
    } else if (t < 64*192 + 64*64) {
        int t2 = t - 64*192; int k = t2 / 64, i = t2 % 64;
        g_B2[t2] = g_M[(64+i)*256 + (64+k)];             // M11^T
    } else if (t < 64*192 + 2*64*64) {
        int t3 = t - 64*192 - 64*64; int k = t3 / 64, i = t3 % 64;
        g_BL[t3] = W_lin[i*64 + k];                      // W_lin^T
    } else if (t < 64*192 + 2*64*64 + 128*320) {
        int t4 = t - 64*192 - 2*64*64;
        int k = t4 / 320, c = t4 % 320;
        float v;
        if      (c < 64)  v = g_M[(128+k)*256 + c];                              // d
        else if (c < 128) v = g_M[(128+k)*256 + c] + g_M[c*256 + 128 + k];       // ce
        else if (c < 192) v = g_M[(c-128)*256 + 128 + k];                        // v
        else              v = g_M[(c-64)*256 + 128 + k];                         // T (for k0)
        g_Bq[t4] = v;
    }
}

__global__ void k_packQA(const float* __restrict__ qst, const float* __restrict__ qrl) {
    int i = blockIdx.x * blockDim.x + threadIdx.x;   // over NQ*128
    int q = i >> 7, k = i & 127;
    g_QA[i] = (k < 64) ? qst[q*64 + k] : qrl[q*64 + k - 64];
}

// tiled GEMM, 64x64 tile, 128 threads, 8x4 accumulators.
// flags bit0: leaky-relu + bias epilogue; bit1: accumulate into C.
__global__ void k_gemmW(const float* __restrict__ A, int lda,
                        const float* __restrict__ B, int ldb,
                        float* __restrict__ C, int ldc,
                        int flags, const float* __restrict__ bias) {
    __shared__ float sAT[64][72];
    __shared__ float sB[64][72];
    int t = threadIdx.x;
    int rb = blockIdx.x * 64, cb = blockIdx.y * 64;
    int r = t >> 4, c4 = (t & 15) * 4;
    for (int rr = r; rr < 64; rr += 8) {
        float4 av = *(const float4*)(A + (size_t)(rb + rr)*lda + c4);
        sAT[c4+0][rr] = av.x; sAT[c4+1][rr] = av.y; sAT[c4+2][rr] = av.z; sAT[c4+3][rr] = av.w;
    }
    for (int kk = r; kk < 64; kk += 8) {
        *(float4*)&sB[kk][c4] = *(const float4*)(B + (size_t)kk*ldb + cb + c4);
    }
    __syncthreads();
    int tx = t & 15, ty = t >> 4;
    int r0 = ty * 8, c0 = tx * 4;
    float acc[8][4] = {};
    #pragma unroll 8
    for (int k = 0; k < 64; k++) {
        float4 a0 = *(const float4*)&sAT[k][r0];
        float4 a1 = *(const float4*)&sAT[k][r0+4];
        float4 bv = *(const float4*)&sB[k][c0];
        float a[8] = {a0.x, a0.y, a0.z, a0.w, a1.x, a1.y, a1.z, a1.w};
        float b[4] = {bv.x, bv.y, bv.z, bv.w};
        #pragma unroll
        for (int ii = 0; ii < 8; ii++)
            #pragma unroll
            for (int jj = 0; jj < 4; jj++)
                acc[ii][jj] = fmaf(a[ii], b[jj], acc[ii][jj]);
    }
    #pragma unroll
    for (int ii = 0; ii < 8; ii++) {
        float* Cp = C + (size_t)(rb + r0 + ii)*ldc + cb + c0;
        float4 o = make_float4(acc[ii][0], acc[ii][1], acc[ii][2], acc[ii][3]);
        if (flags & 2) {
            float4 co = *(const float4*)Cp;
            o.x += co.x; o.y += co.y; o.z += co.z; o.w += co.w;
        }
        if (flags & 1) {
            o.x += bias[cb + c0 + 0]; o.y += bias[cb + c0 + 1];
            o.z += bias[cb + c0 + 2]; o.w += bias[cb + c0 + 3];
            o.x = o.x >= 0.f ? o.x : 0.01f * o.x;
            o.y = o.y >= 0.f ? o.y : 0.01f * o.y;
            o.z = o.z >= 0.f ? o.z : 0.01f * o.z;
            o.w = o.w >= 0.f ? o.w : 0.01f * o.w;
        }
        *(float4*)Cp = o;
    }
}

// quad[e] = rel[e] @ M11^T @ rel[e] : 64 edges/block, 128 threads, 8x4 tile
__global__ void k_quadW(const float* __restrict__ rel, float* __restrict__ quadOut) {
    __shared__ float sAT[64][72];
    __shared__ float sB[64][72];
    int t = threadIdx.x;
    int rb = blockIdx.x * 64;
    int r = t >> 4, c4 = (t & 15) * 4;
    for (int rr = r; rr < 64; rr += 8) {
        float4 av = *(const float4*)(rel + (size_t)(rb + rr)*64 + c4);
        sAT[c4+0][rr] = av.x; sAT[c4+1][rr] = av.y; sAT[c4+2][rr] = av.z; sAT[c4+3][rr] = av.w;
    }
    for (int kk = r; kk < 8; kk += 8) {}  // (B loaded below, full 64 rows)
    for (int kk = r; kk < 64; kk += 8) {
        *(float4*)&sB[kk][c4] = *(const float4*)(g_B2 + kk*64 + c4);
    }
    __syncthreads();
    int tx = t & 15, ty = t >> 4;
    int r0 = ty * 8, c0 = tx * 4;
    float acc[8][4] = {};
    #pragma unroll 8
    for (int k = 0; k < 64; k++) {
        float4 a0 = *(const float4*)&sAT[k][r0];
        float4 a1 = *(const float4*)&sAT[k][r0+4];
        float4 bv = *(const float4*)&sB[k][c0];
        float a[8] = {a0.x, a0.y, a0.z, a0.w, a1.x, a1.y, a1.z, a1.w};
        float b[4] = {bv.x, bv.y, bv.z, bv.w};
        #pragma unroll
        for (int ii = 0; ii < 8; ii++)
            #pragma unroll
            for (int jj = 0; jj < 4; jj++)
                acc[ii][jj] = fmaf(a[ii], b[jj], acc[ii][jj]);
    }
    float qp[8];
    #pragma unroll
    for (int ii = 0; ii < 8; ii++) {
        float4 a = *(const float4*)(rel + (size_t)(rb + r0 + ii)*64 + c0);
        qp[ii] = acc[ii][0]*a.x + acc[ii][1]*a.y + acc[ii][2]*a.z + acc[ii][3]*a.w;
    }
    #pragma unroll
    for (int off = 8; off; off >>= 1)
        #pragma unroll
        for (int ii = 0; ii < 8; ii++)
            qp[ii] += __shfl_down_sync(~0u, qp[ii], off, 16);
    if (tx == 0) {
        #pragma unroll
        for (int ii = 0; ii < 8; ii++) quadOut[rb + r0 + ii] = qp[ii];
    }
}

// k0[q] = QA[q] . QT[q][192:320]
__global__ void k_qk0() {
    int w = (blockIdx.x * blockDim.x + threadIdx.x) >> 5;
    int lane = threadIdx.x & 31;
    if (w >= NQ) return;
    float4 a = *(const float4*)(g_QA + (size_t)w*128 + lane*4);
    float4 b = *(const float4*)(g_QT + (size_t)w*320 + 192 + lane*4);
    float p = a.x*b.x + a.y*b.y + a.z*b.z + a.w*b.w;
    for (int o = 16; o; o >>= 1) p += __shfl_xor_sync(~0u, p, o);
    if (lane == 0) g_Qk0[w] = p;
}

// stage-1 logits: q = edge>>6 deterministic; QT shared per block of 8 edges
__global__ void k_logits1(const int* __restrict__ edges, const float* __restrict__ rel,
                          const float* __restrict__ H, const float* __restrict__ prior,
                          const float* __restrict__ gammaPtr) {
    __shared__ float sQ[192];
    __shared__ float sk0;
    int t = threadIdx.x;
    int q = blockIdx.x >> 3;
    if (t < 192) sQ[t] = g_QT[(size_t)q*320 + t];
    if (t == 192) sk0 = g_Qk0[q];
    __syncthreads();
    int w = blockIdx.x * 8 + (t >> 5);
    int lane = t & 31;
    int src = edges[w*8 + 6], dst = edges[w*8 + 7];
    const float2* hs  = (const float2*)(H + (size_t)src*64);
    const float2* hd  = (const float2*)(H + (size_t)dst*64);
    const float2* nts = (const float2*)(g_nodeT + (size_t)src*192);
    const float2* ntd = (const float2*)(g_nodeT + (size_t)dst*192);
    const float2* rp  = (const float2*)(rel + (size_t)w*64);
    float2 P  = nts[lane];
    float2 U  = nts[32 + lane];
    float2 Wd = ntd[64 + lane];
    float2 hdv = hd[lane], hsv = hs[lane], rv = rp[lane];
    float2 dq = ((const float2*)sQ)[lane];
    float2 cq = ((const float2*)(sQ + 64))[lane];
    float2 vq = ((const float2*)(sQ + 128))[lane];
    float acc = (P.x + dq.x) * hdv.x + (P.y + dq.y) * hdv.y;
    acc = fmaf(rv.x, (U.x + cq.x + Wd.x), acc);
    acc = fmaf(rv.y, (U.y + cq.y + Wd.y), acc);
    acc = fmaf(vq.x, hsv.x, acc);
    acc = fmaf(vq.y, hsv.y, acc);
    for (int o = 16; o; o >>= 1) acc += __shfl_xor_sync(~0u, acc, o);
    if (lane == 0) {
        float l = acc + sk0 + g_quad1[w];
        l = fmaf(gammaPtr[0], prior[w], l);
        g_logit[w] = l;
        g_esrc[w] = src; g_edst[w] = dst;
        atomicMax(&g_segmax[src], encf(l));
    }
}

// stage-0 logits: q random per edge (gathers QT)
__global__ void k_logits0(const int* __restrict__ edges, const float* __restrict__ rel,
                          const float* __restrict__ H, int nE) {
    int w = (blockIdx.x * blockDim.x + threadIdx.x) >> 5;
    int lane = threadIdx.x & 31;
    if (w >= nE) return;
    int q = edges[w*8 + 0], src = edges[w*8 + 6], dst = edges[w*8 + 7];
    const float2* hs  = (const float2*)(H + (size_t)src*64);
    const float2* hd  = (const float2*)(H + (size_t)dst*64);
    const float2* nts = (const float2*)(g_nodeT + (size_t)src*192);
    const float2* ntd = (const float2*)(g_nodeT + (size_t)dst*192);
    const float2* rp  = (const float2*)(rel + (size_t)w*64);
    const float2* qd  = (const float2*)(g_QT + (size_t)q*320);
    const float2* qc  = (const float2*)(g_QT + (size_t)q*320 + 64);
    const float2* qv  = (const float2*)(g_QT + (size_t)q*320 + 128);
    float2 P  = nts[lane];
    float2 U  = nts[32 + lane];
    float2 Wd = ntd[64 + lane];
    float2 hdv = hd[lane], hsv = hs[lane], rv = rp[lane];
    float2 dq = qd[lane], cq = qc[lane], vq = qv[lane];
    float acc = (P.x + dq.x) * hdv.x + (P.y + dq.y) * hdv.y;
    acc = fmaf(rv.x, (U.x + cq.x + Wd.x), acc);
    acc = fmaf(rv.y, (U.y + cq.y + Wd.y), acc);
    acc = fmaf(vq.x, hsv.x, acc);
    acc = fmaf(vq.y, hsv.y, acc);
    for (int o = 16; o; o >>= 1) acc += __shfl_xor_sync(~0u, acc, o);
    if (lane == 0) {
        float l = acc + g_Qk0[q] + g_quad0[w];
        g_logit[w] = l;
        g_esrc[w] = src; g_edst[w] = dst;
        atomicMax(&g_segmax[src], encf(l));
    }
}

// exp(l - max) + segment sum; optional "has src" marking (stage 0)
__global__ void k_pass2(int markHas, int nE) {
    int e = blockIdx.x * blockDim.x + threadIdx.x;
    if (e >= nE) return;
    int src = g_esrc[e];
    float mx = decf(g_segmax[src]);
    float v = expf(g_logit[e] - mx);
    g_logit[e] = v;
    atomicAdd(&g_segsum[src], v);
    if (markHas) g_has[src] = 1;
}

// top-10 of 64 per query
__global__ void k_topk(const int* __restrict__ edges1, const float* __restrict__ score,
                       float* __restrict__ out) {
    int w = (blockIdx.x * blockDim.x + threadIdx.x) >> 5;
    int lane = threadIdx.x & 31;
    if (w >= NQ) return;
    int g0 = lane, g1 = lane + 32;
    int e0 = w*64 + g0, e1 = w*64 + g1;
    int s0 = g_esrc[e0], s1 = g_esrc[e1];
    float tr0 = g_logit[e0] / g_segsum[s0];
    float tr1 = g_logit[e1] / g_segsum[s1];
    float v0 = tr0 * score[s0];
    float v1 = tr1 * score[s1];
    int myG = 0; float myTr = 0.f;
    for (int k = 0; k < KSEL; k++) {
        float bv; int bg; float bt;
        if (v0 >= v1) { bv = v0; bg = g0; bt = tr0; }
        else          { bv = v1; bg = g1; bt = tr1; }
        for (int o = 16; o; o >>= 1) {
            float ov = __shfl_xor_sync(~0u, bv, o);
            int   og = __shfl_xor_sync(~0u, bg, o);
            float ot = __shfl_xor_sync(~0u, bt, o);
            if (ov > bv || (ov == bv && og < bg)) { bv = ov; bg = og; bt = ot; }
        }
        if (lane == k) { myG = bg; myTr = bt; }
        if (g0 == bg) v0 = -__int_as_float(0x7f800000);
        if (g1 == bg) v1 = -__int_as_float(0x7f800000);
    }
    if (lane < KSEL) {
        int orig = w*64 + myG;
        int oi = w*KSEL + lane;
        int src = g_esrc[orig], dst = g_edst[orig];
        g_psrc[oi] = src; g_pdst[oi] = dst; g_ptrans[oi] = myTr;
        g_has[src] = 1;
        atomicAdd(out + dst, myTr * score[src]);
        float* pe = out + OFF_PE + (size_t)oi*8;
        for (int c = 0; c < 8; c++) pe[c] = (float)edges1[orig*8 + c];
        out[OFF_OI + oi] = (float)orig;
    }
}

// Hdst[n] = has[n] ? 0 : Hsrc[n]; optionally build changed-node list
__global__ void k_Hinit(const float* __restrict__ Hsrc, float* __restrict__ Hdst, int buildList) {
    int i = blockIdx.x * blockDim.x + threadIdx.x;
    if (i >= N_NODES * 16) return;
    int n = i >> 4;
    int h = g_has[n];
    float4 v;
    if (h) v = make_float4(0.f, 0.f, 0.f, 0.f);
    else   v = ((const float4*)Hsrc)[i];
    ((float4*)Hdst)[i] = v;
    if (buildList && h && (i & 15) == 0) {
        int idx = atomicAdd(&g_ncnt, 1);
        g_chg[idx] = n;
    }
}

// delta nodeT update: nodeT[node] += (Hnew[node]-Hold[node]) @ B1 over changed list
__global__ void k_dgemm(const float* __restrict__ Hnew, const float* __restrict__ Hold) {
    int cnt = g_ncnt;
    int rb = blockIdx.x * 64;
    if (rb >= cnt) return;
    __shared__ float sAT[64][72];
    __shared__ float sB[64][72];
    __shared__ int snode[64];
    int t = threadIdx.x;
    int cb = blockIdx.y * 64;
    if (t < 64) snode[t] = (rb + t < cnt) ? g_chg[rb + t] : -1;
    __syncthreads();
    int r = t >> 4, c4 = (t & 15) * 4;
    for (int rr = r; rr < 64; rr += 16) {
        int node = snode[rr];
        float4 av = make_float4(0.f, 0.f, 0.f, 0.f);
        if (node >= 0) {
            float4 a = *(const float4*)(Hnew + (size_t)node*64 + c4);
            float4 b = *(const float4*)(Hold + (size_t)node*64 + c4);
            av = make_float4(a.x - b.x, a.y - b.y, a.z - b.z, a.w - b.w);
        }
        sAT[c4+0][rr] = av.x; sAT[c4+1][rr] = av.y; sAT[c4+2][rr] = av.z; sAT[c4+3][rr] = av.w;
    }
    for (int kk = r; kk < 64; kk += 16) {
        *(float4*)&sB[kk][c4] = *(const float4*)(g_B1 + kk*192 + cb + c4);
    }
    __syncthreads();
    int tx = t & 15, ty = t >> 4;
    int r0 = ty * 4, c0 = tx * 4;
    float acc[4][4] = {};
    #pragma unroll 8
    for (int k = 0; k < 64; k++) {
        float4 av = *(const float4*)&sAT[k][r0];
        float4 bv = *(const float4*)&sB[k][c0];
        float a[4] = {av.x, av.y, av.z, av.w};
        float b[4] = {bv.x, bv.y, bv.z, bv.w};
        #pragma unroll
        for (int ii = 0; ii < 4; ii++)
            #pragma unroll
            for (int jj = 0; jj < 4; jj++)
                acc[ii][jj] = fmaf(a[ii], b[jj], acc[ii][jj]);
    }
    #pragma unroll
    for (int ii = 0; ii < 4; ii++) {
        int node = snode[r0 + ii];
        if (node < 0) continue;
        float* Cp = g_nodeT + (size_t)node*192 + cb + c0;
        float4 co = *(const float4*)Cp;
        co.x += acc[ii][0]; co.y += acc[ii][1]; co.z += acc[ii][2]; co.w += acc[ii][3];
        *(float4*)Cp = co;
    }
}

// pruned-edge scatter: H1[src] += trans * H[dst]
__global__ void k_scatter1(const float* __restrict__ H) {
    int w = (blockIdx.x * blockDim.x + threadIdx.x) >> 5;
    int lane = threadIdx.x & 31;
    if (w >= NQ*KSEL) return;
    int src = g_psrc[w], dst = g_pdst[w];
    float t = g_ptrans[w];
    float2 hv = ((const float2*)(H + (size_t)dst*64))[lane];
    atomicAdd(&g_H1[(size_t)src*64 + 2*lane + 0], t * hv.x);
    atomicAdd(&g_H1[(size_t)src*64 + 2*lane + 1], t * hv.y);
}

// edges0 scatter: H2[src] += trans0 * H1[dst]
__global__ void k_scatter0() {
    int w = (blockIdx.x * blockDim.x + threadIdx.x) >> 5;
    int lane = threadIdx.x & 31;
    if (w >= E0N) return;
    int src = g_esrc[w], dst = g_edst[w];
    float t = g_logit[w] / g_segsum[src];
    float2 hv = ((const float2*)(g_H1 + (size_t)dst*64))[lane];
    atomicAdd(&g_H2[(size_t)src*64 + 2*lane + 0], t * hv.x);
    atomicAdd(&g_H2[(size_t)src*64 + 2*lane + 1], t * hv.y);
}

// ---------------- launch ----------------
extern "C" void kernel_launch(void* const* d_in, const int* in_sizes, int n_in,
                              void* d_out, int out_size) {
    const float* score = (const float*)d_in[0];
    const float* H     = (const float*)d_in[1];
    const float* rel0  = (const float*)d_in[2];
    const float* rel1  = (const float*)d_in[3];
    const float* prior = (const float*)d_in[4];
    const float* qst   = (const float*)d_in[5];
    const float* qrl   = (const float*)d_in[6];
    const float* Wq    = (const float*)d_in[7];
    const float* Wk    = (const float*)d_in[8];
    const float* Wlin  = (const float*)d_in[9];
    const float* blin  = (const float*)d_in[10];
    const float* gamma = (const float*)d_in[11];
    const int*   e0    = (const int*)d_in[12];
    const int*   e1    = (const int*)d_in[13];
    float* out = (float*)d_out;

    float *pM, *pWqT, *pNT, *pH1, *pH2, *pB1, *pBL, *pBq, *pQA, *pQT, *pQ1, *pQ0;
    cudaGetSymbolAddress((void**)&pM,  g_M);
    cudaGetSymbolAddress((void**)&pWqT, g_WqT);
    cudaGetSymbolAddress((void**)&pNT, g_nodeT);
    cudaGetSymbolAddress((void**)&pH1, g_H1);
    cudaGetSymbolAddress((void**)&pH2, g_H2);
    cudaGetSymbolAddress((void**)&pB1, g_B1);
    cudaGetSymbolAddress((void**)&pBL, g_BL);
    cudaGetSymbolAddress((void**)&pBq, g_Bq);
    cudaGetSymbolAddress((void**)&pQA, g_QA);
    cudaGetSymbolAddress((void**)&pQT, g_QT);
    cudaGetSymbolAddress((void**)&pQ1, g_quad1);
    cudaGetSymbolAddress((void**)&pQ0, g_quad0);

    k_init1<<<(N_NODES + 255)/256, 256>>>(out);
    k_transQ<<<256, 256>>>(Wq);
    // M = Wq^T @ Wk  (K=256 as 4 accumulating K=64 passes)
    for (int kk = 0; kk < 4; kk++)
        k_gemmW<<<dim3(4, 4), 128>>>(pWqT + kk*64, 256, Wk + kk*64*256, 256, pM, 256,
                                     kk ? 2 : 0, nullptr);
    k_buildB<<<(64*192 + 2*64*64 + 128*320 + 255)/256, 256>>>(Wlin);
    k_packQA<<<NQ*128/256, 256>>>(qst, qrl);

    // query tables: QT = QA @ Bq (K=128 as two accumulating K=64 passes)
    k_gemmW<<<dim3(NQ/64, 5), 128>>>(pQA,      128, pBq,          320, pQT, 320, 0, nullptr);
    k_gemmW<<<dim3(NQ/64, 5), 128>>>(pQA + 64, 128, pBq + 64*320, 320, pQT, 320, 2, nullptr);
    k_qk0<<<NQ*32/256, 256>>>();

    // ---- stage 1 ----
    k_gemmW<<<dim3(N_NODES/64, 3), 128>>>(H, 64, pB1, 192, pNT, 192, 0, nullptr);
    k_quadW<<<E1N/64, 128>>>(rel1, pQ1);
    k_logits1<<<E1N/8, 256>>>(e1, rel1, H, prior, gamma);
    k_pass2<<<E1N/256, 256>>>(0, E1N);
    k_topk<<<NQ/8, 256>>>(e1, score, out);
    k_Hinit<<<(N_NODES*16 + 255)/256, 256>>>(H, pH1, 1);
    k_scatter1<<<(NQ*KSEL)/8, 256>>>(H);

    // ---- stage 0 ----
    k_init2<<<(N_NODES + 255)/256, 256>>>();
    k_dgemm<<<dim3((NQ*KSEL)/64, 3), 256>>>(pH1, H);   // delta update of nodeT
    k_quadW<<<E0N/64, 128>>>(rel0, pQ0);
    k_logits0<<<E0N/8, 256>>>(e0, rel0, pH1, E0N);
    k_pass2<<<E0N/256, 256>>>(1, E0N);
    k_Hinit<<<(N_NODES*16 + 255)/256, 256>>>(pH1, pH2, 0);
    k_scatter0<<<E0N/8, 256>>>();

    // ---- final linear + leaky relu ----
    k_gemmW<<<dim3(N_NODES/64, 1), 128>>>(pH2, 64, pBL, 64, out + OFF_REPR, 64, 1, blin);
}

// round 4
// speedup vs baseline: 1.0569x; 1.0569x over previous
#include <cuda_runtime.h>
#include <cstdint>

#define N_NODES 200000
#define DIM 64
#define NQ 4096
#define GRP 64
#define E1N 262144
#define E0N 131072
#define KSEL 10

// Output layout (f32 concat): score[N], repr[N*64], pruned_edges[Q*K*8], orig_idx[Q*K]
#define OFF_REPR  (N_NODES)
#define OFF_PE    (N_NODES + N_NODES*DIM)
#define OFF_OI    (OFF_PE + NQ*KSEL*8)

// ---------------- scratch (device globals; no allocation) ----------------
__device__ float    g_M [256*256];
__device__ float    g_B1[64*192];       // per-node transform weights: P|U|WdT
__device__ float    g_B2[64*64];        // M11^T
__device__ float    g_BL[64*64];        // W_lin^T
__device__ float    g_Bq[128*320];      // query-table weights: d|ce|v|T
__device__ float    g_QA[NQ*128];       // [qst|qrl]
__device__ float    g_QT[(size_t)NQ*320];
__device__ float    g_Qk0[NQ];
__device__ float    g_nodeT[(size_t)N_NODES*192];
__device__ float    g_quad1[E1N];
__device__ float    g_quad0[E0N];
__device__ float    g_logit[E1N];       // logits, then exp values (in place)
__device__ int      g_esrc[E1N];
__device__ int      g_edst[E1N];
__device__ unsigned g_segmax[N_NODES];
__device__ float    g_segsum[N_NODES];
__device__ int      g_has [N_NODES];    // stage-1 has (persists through stage 0)
__device__ int      g_has0[N_NODES];    // stage-0 has
__device__ float    g_H1[(size_t)N_NODES*DIM];   // sparse: valid only for has rows
__device__ float    g_H2[(size_t)N_NODES*DIM];
__device__ int      g_psrc[NQ*KSEL];
__device__ int      g_pdst[NQ*KSEL];
__device__ float    g_ptrans[NQ*KSEL];
__device__ int      g_chg[NQ*KSEL];
__device__ int      g_ncnt;

// ---------------- helpers ----------------
__device__ __forceinline__ unsigned encf(float f) {
    unsigned u = __float_as_uint(f);
    return (u & 0x80000000u) ? ~u : (u | 0x80000000u);
}
__device__ __forceinline__ float decf(unsigned u) {
    return (u & 0x80000000u) ? __uint_as_float(u & 0x7fffffffu) : __uint_as_float(~u);
}

// ---------------- init kernels ----------------
__global__ void k_init1(float* outScore) {
    int i = blockIdx.x * blockDim.x + threadIdx.x;
    if (i < N_NODES) {
        g_segmax[i] = 0u; g_segsum[i] = 0.f; g_has[i] = 0; g_has0[i] = 0;
        outScore[i] = 0.f;
    }
    if (i == 0) g_ncnt = 0;
}
__global__ void k_init2() {
    int i = blockIdx.x * blockDim.x + threadIdx.x;
    if (i < N_NODES) { g_segmax[i] = 0u; g_segsum[i] = 0.f; }
}

// M = Wq^T @ Wk in ONE kernel. Both operands are K-major already (no transpose).
// 32x64 output tiles, grid (8,4) = 32 blocks, 128 threads, K=256 internal loop.
__global__ void k_gemmM(const float* __restrict__ Wq, const float* __restrict__ Wk) {
    __shared__ float sA[64][36];
    __shared__ float sB[64][72];
    int t = threadIdx.x;
    int ib = blockIdx.x * 32, jb = blockIdx.y * 64;
    int tx = t & 15, ty = t >> 4;
    int r0 = ty * 4, c0 = tx * 4;        // ty 0..7 -> rows 0..31
    float acc[4][4] = {};
    for (int kc = 0; kc < 256; kc += 64) {
        __syncthreads();
        {
            int ra = t >> 3, ca = (t & 7) * 4;
            for (int kk = ra; kk < 64; kk += 16)
                *(float4*)&sA[kk][ca] = *(const float4*)(Wq + (size_t)(kc + kk)*256 + ib + ca);
            int rb_ = t >> 4, cb_ = (t & 15) * 4;
            for (int kk = rb_; kk < 64; kk += 8)
                *(float4*)&sB[kk][cb_] = *(const float4*)(Wk + (size_t)(kc + kk)*256 + jb + cb_);
        }
        __syncthreads();
        #pragma unroll 8
        for (int k = 0; k < 64; k++) {
            float4 av = *(const float4*)&sA[k][r0];
            float4 bv = *(const float4*)&sB[k][c0];
            float a[4] = {av.x, av.y, av.z, av.w};
            float b[4] = {bv.x, bv.y, bv.z, bv.w};
            #pragma unroll
            for (int ii = 0; ii < 4; ii++)
                #pragma unroll
                for (int jj = 0; jj < 4; jj++)
                    acc[ii][jj] = fmaf(a[ii], b[jj], acc[ii][jj]);
        }
    }
    #pragma unroll
    for (int ii = 0; ii < 4; ii++) {
        float4 o = make_float4(acc[ii][0], acc[ii][1], acc[ii][2], acc[ii][3]);
        *(float4*)(g_M + (size_t)(ib + r0 + ii)*256 + jb + c0) = o;
    }
}

__global__ void k_buildB(const float* __restrict__ W_lin) {
    int t = blockIdx.x * blockDim.x + threadIdx.x;
    if (t < 64*192) {
        int k = t / 192, c = t % 192;
        float v;
        if (c < 128) v = g_M[k*256 + c];                 // M00|M01
        else         v = g_M[(64 + (c-128))*256 + k];    // M10^T
        g_B1[t] = v;
    } else if (t < 64*192 + 64*64) {
        int t2 = t - 64*192; int k = t2 / 64, i = t2 % 64;
        g_B2[t2] = g_M[(64+i)*256 + (64+k)];             // M11^T
    } else if (t < 64*192 + 2*64*64) {
        int t3 = t - 64*192 - 64*64; int k = t3 / 64, i = t3 % 64;
        g_BL[t3] = W_lin[i*64 + k];                      // W_lin^T
    } else if (t < 64*192 + 2*64*64 + 128*320) {
        int t4 = t - 64*192 - 2*64*64;
        int k = t4 / 320, c = t4 % 320;
        float v;
        if      (c < 64)  v = g_M[(128+k)*256 + c];                              // d
        else if (c < 128) v = g_M[(128+k)*256 + c] + g_M[c*256 + 128 + k];       // ce
        else if (c < 192) v = g_M[(c-128)*256 + 128 + k];                        // v
        else              v = g_M[(c-64)*256 + 128 + k];                         // T (for k0)
        g_Bq[t4] = v;
    }
}

__global__ void k_packQA(const float* __restrict__ qst, const float* __restrict__ qrl) {
    int i = blockIdx.x * blockDim.x + threadIdx.x;   // over NQ*128
    int q = i >> 7, k = i & 127;
    g_QA[i] = (k < 64) ? qst[q*64 + k] : qrl[q*64 + k - 64];
}

// tiled GEMM, 64x64 tile, 128 threads, 8x4 accumulators.
// flags bit0: leaky-relu + bias epilogue; bit1: accumulate into C.
__global__ void k_gemmW(const float* __restrict__ A, int lda,
                        const float* __restrict__ B, int ldb,
                        float* __restrict__ C, int ldc,
                        int flags, const float* __restrict__ bias) {
    __shared__ float sAT[64][72];
    __shared__ float sB[64][72];
    int t = threadIdx.x;
    int rb = blockIdx.x * 64, cb = blockIdx.y * 64;
    int r = t >> 4, c4 = (t & 15) * 4;
    for (int rr = r; rr < 64; rr += 8) {
        float4 av = *(const float4*)(A + (size_t)(rb + rr)*lda + c4);
        sAT[c4+0][rr] = av.x; sAT[c4+1][rr] = av.y; sAT[c4+2][rr] = av.z; sAT[c4+3][rr] = av.w;
    }
    for (int kk = r; kk < 64; kk += 8) {
        *(float4*)&sB[kk][c4] = *(const float4*)(B + (size_t)kk*ldb + cb + c4);
    }
    __syncthreads();
    int tx = t & 15, ty = t >> 4;
    int r0 = ty * 8, c0 = tx * 4;
    float acc[8][4] = {};
    #pragma unroll 8
    for (int k = 0; k < 64; k++) {
        float4 a0 = *(const float4*)&sAT[k][r0];
        float4 a1 = *(const float4*)&sAT[k][r0+4];
        float4 bv = *(const float4*)&sB[k][c0];
        float a[8] = {a0.x, a0.y, a0.z, a0.w, a1.x, a1.y, a1.z, a1.w};
        float b[4] = {bv.x, bv.y, bv.z, bv.w};
        #pragma unroll
        for (int ii = 0; ii < 8; ii++)
            #pragma unroll
            for (int jj = 0; jj < 4; jj++)
                acc[ii][jj] = fmaf(a[ii], b[jj], acc[ii][jj]);
    }
    #pragma unroll
    for (int ii = 0; ii < 8; ii++) {
        float* Cp = C + (size_t)(rb + r0 + ii)*ldc + cb + c0;
        float4 o = make_float4(acc[ii][0], acc[ii][1], acc[ii][2], acc[ii][3]);
        if (flags & 2) {
            float4 co = *(const float4*)Cp;
            o.x += co.x; o.y += co.y; o.z += co.z; o.w += co.w;
        }
        if (flags & 1) {
            o.x += bias[cb + c0 + 0]; o.y += bias[cb + c0 + 1];
            o.z += bias[cb + c0 + 2]; o.w += bias[cb + c0 + 3];
            o.x = o.x >= 0.f ? o.x : 0.01f * o.x;
            o.y = o.y >= 0.f ? o.y : 0.01f * o.y;
            o.z = o.z >= 0.f ? o.z : 0.01f * o.z;
            o.w = o.w >= 0.f ? o.w : 0.01f * o.w;
        }
        *(float4*)Cp = o;
    }
}

// quad[e] = rel[e] @ M11^T @ rel[e] : 64 edges/block, 128 threads, 8x4 tile
__global__ void k_quadW(const float* __restrict__ rel, float* __restrict__ quadOut) {
    __shared__ float sAT[64][72];
    __shared__ float sB[64][72];
    int t = threadIdx.x;
    int rb = blockIdx.x * 64;
    int r = t >> 4, c4 = (t & 15) * 4;
    for (int rr = r; rr < 64; rr += 8) {
        float4 av = *(const float4*)(rel + (size_t)(rb + rr)*64 + c4);
        sAT[c4+0][rr] = av.x; sAT[c4+1][rr] = av.y; sAT[c4+2][rr] = av.z; sAT[c4+3][rr] = av.w;
    }
    for (int kk = r; kk < 64; kk += 8) {
        *(float4*)&sB[kk][c4] = *(const float4*)(g_B2 + kk*64 + c4);
    }
    __syncthreads();
    int tx = t & 15, ty = t >> 4;
    int r0 = ty * 8, c0 = tx * 4;
    float acc[8][4] = {};
    #pragma unroll 8
    for (int k = 0; k < 64; k++) {
        float4 a0 = *(const float4*)&sAT[k][r0];
        float4 a1 = *(const float4*)&sAT[k][r0+4];
        float4 bv = *(const float4*)&sB[k][c0];
        float a[8] = {a0.x, a0.y, a0.z, a0.w, a1.x, a1.y, a1.z, a1.w};
        float b[4] = {bv.x, bv.y, bv.z, bv.w};
        #pragma unroll
        for (int ii = 0; ii < 8; ii++)
            #pragma unroll
            for (int jj = 0; jj < 4; jj++)
                acc[ii][jj] = fmaf(a[ii], b[jj], acc[ii][jj]);
    }
    float qp[8];
    #pragma unroll
    for (int ii = 0; ii < 8; ii++) {
        float4 a = *(const float4*)(rel + (size_t)(rb + r0 + ii)*64 + c0);
        qp[ii] = acc[ii][0]*a.x + acc[ii][1]*a.y + acc[ii][2]*a.z + acc[ii][3]*a.w;
    }
    #pragma unroll
    for (int off = 8; off; off >>= 1)
        #pragma unroll
        for (int ii = 0; ii < 8; ii++)
            qp[ii] += __shfl_down_sync(~0u, qp[ii], off, 16);
    if (tx == 0) {
        #pragma unroll
        for (int ii = 0; ii < 8; ii++) quadOut[rb + r0 + ii] = qp[ii];
    }
}

// k0[q] = QA[q] . QT[q][192:320]
__global__ void k_qk0() {
    int w = (blockIdx.x * blockDim.x + threadIdx.x) >> 5;
    int lane = threadIdx.x & 31;
    if (w >= NQ) return;
    float4 a = *(const float4*)(g_QA + (size_t)w*128 + lane*4);
    float4 b = *(const float4*)(g_QT + (size_t)w*320 + 192 + lane*4);
    float p = a.x*b.x + a.y*b.y + a.z*b.z + a.w*b.w;
    for (int o = 16; o; o >>= 1) p += __shfl_xor_sync(~0u, p, o);
    if (lane == 0) g_Qk0[w] = p;
}

// stage-1 logits: q = edge>>6 deterministic; QT shared per block of 8 edges
__global__ void k_logits1(const int* __restrict__ edges, const float* __restrict__ rel,
                          const float* __restrict__ H, const float* __restrict__ prior,
                          const float* __restrict__ gammaPtr) {
    __shared__ float sQ[192];
    __shared__ float sk0;
    int t = threadIdx.x;
    int q = blockIdx.x >> 3;
    if (t < 192) sQ[t] = g_QT[(size_t)q*320 + t];
    if (t == 192) sk0 = g_Qk0[q];
    __syncthreads();
    int w = blockIdx.x * 8 + (t >> 5);
    int lane = t & 31;
    int src = edges[w*8 + 6], dst = edges[w*8 + 7];
    const float2* hs  = (const float2*)(H + (size_t)src*64);
    const float2* hd  = (const float2*)(H + (size_t)dst*64);
    const float2* nts = (const float2*)(g_nodeT + (size_t)src*192);
    const float2* ntd = (const float2*)(g_nodeT + (size_t)dst*192);
    const float2* rp  = (const float2*)(rel + (size_t)w*64);
    float2 P  = nts[lane];
    float2 U  = nts[32 + lane];
    float2 Wd = ntd[64 + lane];
    float2 hdv = hd[lane], hsv = hs[lane], rv = rp[lane];
    float2 dq = ((const float2*)sQ)[lane];
    float2 cq = ((const float2*)(sQ + 64))[lane];
    float2 vq = ((const float2*)(sQ + 128))[lane];
    float acc = (P.x + dq.x) * hdv.x + (P.y + dq.y) * hdv.y;
    acc = fmaf(rv.x, (U.x + cq.x + Wd.x), acc);
    acc = fmaf(rv.y, (U.y + cq.y + Wd.y), acc);
    acc = fmaf(vq.x, hsv.x, acc);
    acc = fmaf(vq.y, hsv.y, acc);
    for (int o = 16; o; o >>= 1) acc += __shfl_xor_sync(~0u, acc, o);
    if (lane == 0) {
        float l = acc + sk0 + g_quad1[w];
        l = fmaf(gammaPtr[0], prior[w], l);
        g_logit[w] = l;
        g_esrc[w] = src; g_edst[w] = dst;
        atomicMax(&g_segmax[src], encf(l));
    }
}

// stage-0 logits: q random per edge; H1 virtual = has ? H1s : H
__global__ void k_logits0(const int* __restrict__ edges, const float* __restrict__ rel,
                          const float* __restrict__ H, int nE) {
    int w = (blockIdx.x * blockDim.x + threadIdx.x) >> 5;
    int lane = threadIdx.x & 31;
    if (w >= nE) return;
    int q = edges[w*8 + 0], src = edges[w*8 + 6], dst = edges[w*8 + 7];
    const float* Hs = g_has[src] ? (const float*)g_H1 : H;
    const float* Hd = g_has[dst] ? (const float*)g_H1 : H;
    const float2* hs  = (const float2*)(Hs + (size_t)src*64);
    const float2* hd  = (const float2*)(Hd + (size_t)dst*64);
    const float2* nts = (const float2*)(g_nodeT + (size_t)src*192);
    const float2* ntd = (const float2*)(g_nodeT + (size_t)dst*192);
    const float2* rp  = (const float2*)(rel + (size_t)w*64);
    const float2* qd  = (const float2*)(g_QT + (size_t)q*320);
    const float2* qc  = (const float2*)(g_QT + (size_t)q*320 + 64);
    const float2* qv  = (const float2*)(g_QT + (size_t)q*320 + 128);
    float2 P  = nts[lane];
    float2 U  = nts[32 + lane];
    float2 Wd = ntd[64 + lane];
    float2 hdv = hd[lane], hsv = hs[lane], rv = rp[lane];
    float2 dq = qd[lane], cq = qc[lane], vq = qv[lane];
    float acc = (P.x + dq.x) * hdv.x + (P.y + dq.y) * hdv.y;
    acc = fmaf(rv.x, (U.x + cq.x + Wd.x), acc);
    acc = fmaf(rv.y, (U.y + cq.y + Wd.y), acc);
    acc = fmaf(vq.x, hsv.x, acc);
    acc = fmaf(vq.y, hsv.y, acc);
    for (int o = 16; o; o >>= 1) acc += __shfl_xor_sync(~0u, acc, o);
    if (lane == 0) {
        float l = acc + g_Qk0[q] + g_quad0[w];
        g_logit[w] = l;
        g_esrc[w] = src; g_edst[w] = dst;
        atomicMax(&g_segmax[src], encf(l));
    }
}

// exp(l - max) + segment sum; optional has0 marking (stage 0)
__global__ void k_pass2(int markHas, int nE) {
    int e = blockIdx.x * blockDim.x + threadIdx.x;
    if (e >= nE) return;
    int src = g_esrc[e];
    float mx = decf(g_segmax[src]);
    float v = expf(g_logit[e] - mx);
    g_logit[e] = v;
    atomicAdd(&g_segsum[src], v);
    if (markHas) g_has0[src] = 1;
}

// top-10 of 64 per query
__global__ void k_topk(const int* __restrict__ edges1, const float* __restrict__ score,
                       float* __restrict__ out) {
    int w = (blockIdx.x * blockDim.x + threadIdx.x) >> 5;
    int lane = threadIdx.x & 31;
    if (w >= NQ) return;
    int g0 = lane, g1 = lane + 32;
    int e0 = w*64 + g0, e1 = w*64 + g1;
    int s0 = g_esrc[e0], s1 = g_esrc[e1];
    float tr0 = g_logit[e0] / g_segsum[s0];
    float tr1 = g_logit[e1] / g_segsum[s1];
    float v0 = tr0 * score[s0];
    float v1 = tr1 * score[s1];
    int myG = 0; float myTr = 0.f;
    for (int k = 0; k < KSEL; k++) {
        float bv; int bg; float bt;
        if (v0 >= v1) { bv = v0; bg = g0; bt = tr0; }
        else          { bv = v1; bg = g1; bt = tr1; }
        for (int o = 16; o; o >>= 1) {
            float ov = __shfl_xor_sync(~0u, bv, o);
            int   og = __shfl_xor_sync(~0u, bg, o);
            float ot = __shfl_xor_sync(~0u, bt, o);
            if (ov > bv || (ov == bv && og < bg)) { bv = ov; bg = og; bt = ot; }
        }
        if (lane == k) { myG = bg; myTr = bt; }
        if (g0 == bg) v0 = -__int_as_float(0x7f800000);
        if (g1 == bg) v1 = -__int_as_float(0x7f800000);
    }
    if (lane < KSEL) {
        int orig = w*64 + myG;
        int oi = w*KSEL + lane;
        int src = g_esrc[orig], dst = g_edst[orig];
        g_psrc[oi] = src; g_pdst[oi] = dst; g_ptrans[oi] = myTr;
        g_has[src] = 1;
        atomicAdd(out + dst, myTr * score[src]);
        float* pe = out + OFF_PE + (size_t)oi*8;
        for (int c = 0; c < 8; c++) pe[c] = (float)edges1[orig*8 + c];
        out[OFF_OI + oi] = (float)orig;
    }
}

// build changed-node list from has flags
__global__ void k_mklist() {
    int i = blockIdx.x * blockDim.x + threadIdx.x;
    if (i < N_NODES && g_has[i]) {
        int idx = atomicAdd(&g_ncnt, 1);
        g_chg[idx] = i;
    }
}

// zero H1 rows for changed nodes (one warp per row)
__global__ void k_zeroChg() {
    int w = (blockIdx.x * blockDim.x + threadIdx.x) >> 5;
    int lane = threadIdx.x & 31;
    if (w >= g_ncnt) return;
    int n = g_chg[w];
    ((float2*)(g_H1 + (size_t)n*64))[lane] = make_float2(0.f, 0.f);
}

// pruned-edge scatter: H1s[src] += trans * H[dst]   (src always a has-row)
__global__ void k_scatter1(const float* __restrict__ H) {
    int w = (blockIdx.x * blockDim.x + threadIdx.x) >> 5;
    int lane = threadIdx.x & 31;
    if (w >= NQ*KSEL) return;
    int src = g_psrc[w], dst = g_pdst[w];
    float t = g_ptrans[w];
    float2 hv = ((const float2*)(H + (size_t)dst*64))[lane];
    atomicAdd(&g_H1[(size_t)src*64 + 2*lane + 0], t * hv.x);
    atomicAdd(&g_H1[(size_t)src*64 + 2*lane + 1], t * hv.y);
}

// delta nodeT update: nodeT[node] += (H1s[node]-H[node]) @ B1 over changed list
__global__ void k_dgemm(const float* __restrict__ Hold) {
    int cnt = g_ncnt;
    int rb = blockIdx.x * 64;
    if (rb >= cnt) return;
    __shared__ float sAT[64][72];
    __shared__ float sB[64][72];
    __shared__ int snode[64];
    int t = threadIdx.x;
    int cb = blockIdx.y * 64;
    if (t < 64) snode[t] = (rb + t < cnt) ? g_chg[rb + t] : -1;
    __syncthreads();
    int r = t >> 4, c4 = (t & 15) * 4;
    for (int rr = r; rr < 64; rr += 16) {
        int node = snode[rr];
        float4 av = make_float4(0.f, 0.f, 0.f, 0.f);
        if (node >= 0) {
            float4 a = *(const float4*)(g_H1 + (size_t)node*64 + c4);
            float4 b = *(const float4*)(Hold + (size_t)node*64 + c4);
            av = make_float4(a.x - b.x, a.y - b.y, a.z - b.z, a.w - b.w);
        }
        sAT[c4+0][rr] = av.x; sAT[c4+1][rr] = av.y; sAT[c4+2][rr] = av.z; sAT[c4+3][rr] = av.w;
    }
    for (int kk = r; kk < 64; kk += 16) {
        *(float4*)&sB[kk][c4] = *(const float4*)(g_B1 + kk*192 + cb + c4);
    }
    __syncthreads();
    int tx = t & 15, ty = t >> 4;
    int r0 = ty * 4, c0 = tx * 4;
    float acc[4][4] = {};
    #pragma unroll 8
    for (int k = 0; k < 64; k++) {
        float4 av = *(const float4*)&sAT[k][r0];
        float4 bv = *(const float4*)&sB[k][c0];
        float a[4] = {av.x, av.y, av.z, av.w};
        float b[4] = {bv.x, bv.y, bv.z, bv.w};
        #pragma unroll
        for (int ii = 0; ii < 4; ii++)
            #pragma unroll
            for (int jj = 0; jj < 4; jj++)
                acc[ii][jj] = fmaf(a[ii], b[jj], acc[ii][jj]);
    }
    #pragma unroll
    for (int ii = 0; ii < 4; ii++) {
        int node = snode[r0 + ii];
        if (node < 0) continue;
        float* Cp = g_nodeT + (size_t)node*192 + cb + c0;
        float4 co = *(const float4*)Cp;
        co.x += acc[ii][0]; co.y += acc[ii][1]; co.z += acc[ii][2]; co.w += acc[ii][3];
        *(float4*)Cp = co;
    }
}

// H2[n] = has0 ? 0 : (has1 ? H1s[n] : H[n])
__global__ void k_Hinit0(const float* __restrict__ H) {
    int i = blockIdx.x * blockDim.x + threadIdx.x;
    if (i >= N_NODES * 16) return;
    int n = i >> 4;
    float4 v = make_float4(0.f, 0.f, 0.f, 0.f);
    if (!g_has0[n]) {
        const float* src = g_has[n] ? (const float*)g_H1 : H;
        v = ((const float4*)src)[i];
    }
    ((float4*)g_H2)[i] = v;
}

// edges0 scatter: H2[src] += trans0 * H1virtual[dst]
__global__ void k_scatter0(const float* __restrict__ H) {
    int w = (blockIdx.x * blockDim.x + threadIdx.x) >> 5;
    int lane = threadIdx.x & 31;
    if (w >= E0N) return;
    int src = g_esrc[w], dst = g_edst[w];
    float t = g_logit[w] / g_segsum[src];
    const float* Hd = g_has[dst] ? (const float*)g_H1 : H;
    float2 hv = ((const float2*)(Hd + (size_t)dst*64))[lane];
    atomicAdd(&g_H2[(size_t)src*64 + 2*lane + 0], t * hv.x);
    atomicAdd(&g_H2[(size_t)src*64 + 2*lane + 1], t * hv.y);
}

// ---------------- launch ----------------
extern "C" void kernel_launch(void* const* d_in, const int* in_sizes, int n_in,
                              void* d_out, int out_size) {
    const float* score = (const float*)d_in[0];
    const float* H     = (const float*)d_in[1];
    const float* rel0  = (const float*)d_in[2];
    const float* rel1  = (const float*)d_in[3];
    const float* prior = (const float*)d_in[4];
    const float* qst   = (const float*)d_in[5];
    const float* qrl   = (const float*)d_in[6];
    const float* Wq    = (const float*)d_in[7];
    const float* Wk    = (const float*)d_in[8];
    const float* Wlin  = (const float*)d_in[9];
    const float* blin  = (const float*)d_in[10];
    const float* gamma = (const float*)d_in[11];
    const int*   e0    = (const int*)d_in[12];
    const int*   e1    = (const int*)d_in[13];
    float* out = (float*)d_out;

    float *pNT, *pH2, *pB1, *pBL, *pBq, *pQA, *pQT, *pQ1, *pQ0;
    cudaGetSymbolAddress((void**)&pNT, g_nodeT);
    cudaGetSymbolAddress((void**)&pH2, g_H2);
    cudaGetSymbolAddress((void**)&pB1, g_B1);
    cudaGetSymbolAddress((void**)&pBL, g_BL);
    cudaGetSymbolAddress((void**)&pBq, g_Bq);
    cudaGetSymbolAddress((void**)&pQA, g_QA);
    cudaGetSymbolAddress((void**)&pQT, g_QT);
    cudaGetSymbolAddress((void**)&pQ1, g_quad1);
    cudaGetSymbolAddress((void**)&pQ0, g_quad0);

    k_init1<<<(N_NODES + 255)/256, 256>>>(out);
    k_gemmM<<<dim3(8, 4), 128>>>(Wq, Wk);
    k_buildB<<<(64*192 + 2*64*64 + 128*320 + 255)/256, 256>>>(Wlin);
    k_packQA<<<NQ*128/256, 256>>>(qst, qrl);

    // query tables: QT = QA @ Bq (K=128 as two accumulating K=64 passes)
    k_gemmW<<<dim3(NQ/64, 5), 128>>>(pQA,      128, pBq,          320, pQT, 320, 0, nullptr);
    k_gemmW<<<dim3(NQ/64, 5), 128>>>(pQA + 64, 128, pBq + 64*320, 320, pQT, 320, 2, nullptr);
    k_qk0<<<NQ*32/256, 256>>>();

    // ---- stage 1 ----
    k_gemmW<<<dim3(N_NODES/64, 3), 128>>>(H, 64, pB1, 192, pNT, 192, 0, nullptr);
    k_quadW<<<E1N/64, 128>>>(rel1, pQ1);
    k_logits1<<<E1N/8, 256>>>(e1, rel1, H, prior, gamma);
    k_pass2<<<E1N/256, 256>>>(0, E1N);
    k_topk<<<NQ/8, 256>>>(e1, score, out);
    k_mklist<<<(N_NODES + 255)/256, 256>>>();
    k_zeroChg<<<(NQ*KSEL)/8, 256>>>();
    k_scatter1<<<(NQ*KSEL)/8, 256>>>(H);

    // ---- stage 0 ----
    k_init2<<<(N_NODES + 255)/256, 256>>>();
    k_dgemm<<<dim3((NQ*KSEL)/64, 3), 256>>>(H);        // delta update of nodeT
    k_quadW<<<E0N/64, 128>>>(rel0, pQ0);
    k_logits0<<<E0N/8, 256>>>(e0, rel0, H, E0N);
    k_pass2<<<E0N/256, 256>>>(1, E0N);
    k_Hinit0<<<(N_NODES*16 + 255)/256, 256>>>(H);
    k_scatter0<<<E0N/8, 256>>>(H);

    // ---- final linear + leaky relu ----
    k_gemmW<<<dim3(N_NODES/64, 1), 128>>>(pH2, 64, pBL, 64, out + OFF_REPR, 64, 1, blin);
}

// round 5
// speedup vs baseline: 1.1694x; 1.1064x over previous
#include <cuda_runtime.h>
#include <cstdint>

#define N_NODES 200000
#define DIM 64
#define NQ 4096
#define GRP 64
#define E1N 262144
#define E0N 131072
#define KSEL 10

#define OFF_REPR  (N_NODES)
#define OFF_PE    (N_NODES + N_NODES*DIM)
#define OFF_OI    (OFF_PE + NQ*KSEL*8)

// ---------------- scratch ----------------
__device__ float    g_M [256*256];
__device__ float    g_B1[64*192];
__device__ float    g_B2[64*64];
__device__ float    g_BL[64*64];
__device__ float    g_Bq[128*320];
__device__ float    g_QA[NQ*128];
__device__ float    g_QT[(size_t)NQ*320];
__device__ float    g_Qk0[NQ];
__device__ float    g_nodeT[(size_t)N_NODES*192];
__device__ float    g_quad1[E1N];
__device__ float    g_quad0[E0N];
__device__ float    g_logit[E1N];
__device__ int      g_esrc[E1N];
__device__ int      g_edst[E1N];
__device__ unsigned g_segmax [N_NODES];
__device__ float    g_segsum [N_NODES];
__device__ unsigned g_segmax0[N_NODES];
__device__ float    g_segsum0[N_NODES];
__device__ int      g_has [N_NODES];
__device__ int      g_has0[N_NODES];
__device__ float    g_H1[(size_t)N_NODES*DIM];
__device__ float    g_H2[(size_t)N_NODES*DIM];
__device__ int      g_psrc[NQ*KSEL];
__device__ int      g_pdst[NQ*KSEL];
__device__ float    g_ptrans[NQ*KSEL];
__device__ int      g_chg[NQ*KSEL];
__device__ int      g_ncnt;

__device__ __forceinline__ unsigned encf(float f) {
    unsigned u = __float_as_uint(f);
    return (u & 0x80000000u) ? ~u : (u | 0x80000000u);
}
__device__ __forceinline__ float decf(unsigned u) {
    return (u & 0x80000000u) ? __uint_as_float(u & 0x7fffffffu) : __uint_as_float(~u);
}

// ---------------- init ----------------
__global__ void k_init1(float* outScore) {
    int i = blockIdx.x * blockDim.x + threadIdx.x;
    if (i < N_NODES) {
        g_segmax[i] = 0u;  g_segsum[i] = 0.f;
        g_segmax0[i] = 0u; g_segsum0[i] = 0.f;
        g_has[i] = 0; g_has0[i] = 0;
        outScore[i] = 0.f;
    }
    if (i == 0) g_ncnt = 0;
}

// M = Wq^T @ Wk (32x64 tiles, grid (8,4))
__global__ void k_gemmM(const float* __restrict__ Wq, const float* __restrict__ Wk) {
    __shared__ float sA[64][36];
    __shared__ float sB[64][72];
    int t = threadIdx.x;
    int ib = blockIdx.x * 32, jb = blockIdx.y * 64;
    int tx = t & 15, ty = t >> 4;
    int r0 = ty * 4, c0 = tx * 4;
    float acc[4][4] = {};
    for (int kc = 0; kc < 256; kc += 64) {
        __syncthreads();
        {
            int ra = t >> 3, ca = (t & 7) * 4;
            for (int kk = ra; kk < 64; kk += 16)
                *(float4*)&sA[kk][ca] = *(const float4*)(Wq + (size_t)(kc + kk)*256 + ib + ca);
            int rb_ = t >> 4, cb_ = (t & 15) * 4;
            for (int kk = rb_; kk < 64; kk += 8)
                *(float4*)&sB[kk][cb_] = *(const float4*)(Wk + (size_t)(kc + kk)*256 + jb + cb_);
        }
        __syncthreads();
        #pragma unroll 8
        for (int k = 0; k < 64; k++) {
            float4 av = *(const float4*)&sA[k][r0];
            float4 bv = *(const float4*)&sB[k][c0];
            float a[4] = {av.x, av.y, av.z, av.w};
            float b[4] = {bv.x, bv.y, bv.z, bv.w};
            #pragma unroll
            for (int ii = 0; ii < 4; ii++)
                #pragma unroll
                for (int jj = 0; jj < 4; jj++)
                    acc[ii][jj] = fmaf(a[ii], b[jj], acc[ii][jj]);
        }
    }
    #pragma unroll
    for (int ii = 0; ii < 4; ii++)
        *(float4*)(g_M + (size_t)(ib + r0 + ii)*256 + jb + c0) =
            make_float4(acc[ii][0], acc[ii][1], acc[ii][2], acc[ii][3]);
}

__global__ void k_buildB(const float* __restrict__ W_lin) {
    int t = blockIdx.x * blockDim.x + threadIdx.x;
    if (t < 64*192) {
        int k = t / 192, c = t % 192;
        float v;
        if (c < 128) v = g_M[k*256 + c];
        else         v = g_M[(64 + (c-128))*256 + k];
        g_B1[t] = v;
    } else if (t < 64*192 + 64*64) {
        int t2 = t - 64*192; int k = t2 / 64, i = t2 % 64;
        g_B2[t2] = g_M[(64+i)*256 + (64+k)];
    } else if (t < 64*192 + 2*64*64) {
        int t3 = t - 64*192 - 64*64; int k = t3 / 64, i = t3 % 64;
        g_BL[t3] = W_lin[i*64 + k];
    } else if (t < 64*192 + 2*64*64 + 128*320) {
        int t4 = t - 64*192 - 2*64*64;
        int k = t4 / 320, c = t4 % 320;
        float v;
        if      (c < 64)  v = g_M[(128+k)*256 + c];
        else if (c < 128) v = g_M[(128+k)*256 + c] + g_M[c*256 + 128 + k];
        else if (c < 192) v = g_M[(c-128)*256 + 128 + k];
        else              v = g_M[(c-64)*256 + 128 + k];
        g_Bq[t4] = v;
    }
}

__global__ void k_packQA(const float* __restrict__ qst, const float* __restrict__ qrl) {
    int i = blockIdx.x * blockDim.x + threadIdx.x;
    int q = i >> 7, k = i & 127;
    g_QA[i] = (k < 64) ? qst[q*64 + k] : qrl[q*64 + k - 64];
}

// QT = QA @ Bq : 64x64 tiles, K=128 internal loop, 128 threads, 8x4 acc
__global__ void k_gemmQ() {
    __shared__ float sAT[64][72];
    __shared__ float sB[64][72];
    int t = threadIdx.x;
    int rb = blockIdx.x * 64, cb = blockIdx.y * 64;
    int tx = t & 15, ty = t >> 4;
    int r0 = ty * 8, c0 = tx * 4;
    float acc[8][4] = {};
    for (int kc = 0; kc < 128; kc += 64) {
        __syncthreads();
        {
            int r = t >> 4, c4 = (t & 15) * 4;
            for (int rr = r; rr < 64; rr += 8) {
                float4 av = *(const float4*)(g_QA + (size_t)(rb + rr)*128 + kc + c4);
                sAT[c4+0][rr] = av.x; sAT[c4+1][rr] = av.y;
                sAT[c4+2][rr] = av.z; sAT[c4+3][rr] = av.w;
            }
            for (int kk = r; kk < 64; kk += 8)
                *(float4*)&sB[kk][c4] = *(const float4*)(g_Bq + (size_t)(kc + kk)*320 + cb + c4);
        }
        __syncthreads();
        #pragma unroll 8
        for (int k = 0; k < 64; k++) {
            float4 a0 = *(const float4*)&sAT[k][r0];
            float4 a1 = *(const float4*)&sAT[k][r0+4];
            float4 bv = *(const float4*)&sB[k][c0];
            float a[8] = {a0.x, a0.y, a0.z, a0.w, a1.x, a1.y, a1.z, a1.w};
            float b[4] = {bv.x, bv.y, bv.z, bv.w};
            #pragma unroll
            for (int ii = 0; ii < 8; ii++)
                #pragma unroll
                for (int jj = 0; jj < 4; jj++)
                    acc[ii][jj] = fmaf(a[ii], b[jj], acc[ii][jj]);
        }
    }
    #pragma unroll
    for (int ii = 0; ii < 8; ii++)
        *(float4*)(g_QT + (size_t)(rb + r0 + ii)*320 + cb + c0) =
            make_float4(acc[ii][0], acc[ii][1], acc[ii][2], acc[ii][3]);
}

__global__ void k_qk0() {
    int w = (blockIdx.x * blockDim.x + threadIdx.x) >> 5;
    int lane = threadIdx.x & 31;
    if (w >= NQ) return;
    float4 a = *(const float4*)(g_QA + (size_t)w*128 + lane*4);
    float4 b = *(const float4*)(g_QT + (size_t)w*320 + 192 + lane*4);
    float p = a.x*b.x + a.y*b.y + a.z*b.z + a.w*b.w;
    for (int o = 16; o; o >>= 1) p += __shfl_xor_sync(~0u, p, o);
    if (lane == 0) g_Qk0[w] = p;
}

// nodeT = H @ B1 : 64x192 tile per block, 256 threads, 4x12 acc, B1 fully smem-resident.
extern __shared__ float smN[];
__global__ void k_gemmN(const float* __restrict__ A) {
    float (*sAT)[68] = (float(*)[68])smN;             // [64][68]
    float (*sB)[196] = (float(*)[196])(smN + 64*68);  // [64][196]
    int t = threadIdx.x;
    int rb = blockIdx.x * 64;
    {
        int r = t >> 4, c4 = (t & 15) * 4;
        for (int rr = r; rr < 64; rr += 16) {
            float4 av = *(const float4*)(A + (size_t)(rb + rr)*64 + c4);
            sAT[c4+0][rr] = av.x; sAT[c4+1][rr] = av.y;
            sAT[c4+2][rr] = av.z; sAT[c4+3][rr] = av.w;
        }
        for (int kk = r; kk < 64; kk += 16) {
            #pragma unroll
            for (int co = 0; co < 3; co++)
                *(float4*)&sB[kk][c4 + co*64] = *(const float4*)(g_B1 + (size_t)kk*192 + c4 + co*64);
        }
    }
    __syncthreads();
    int tx = t & 15, ty = t >> 4;
    int r0 = ty * 4, c0 = tx * 4;
    float acc[4][12] = {};
    #pragma unroll 4
    for (int k = 0; k < 64; k++) {
        float4 av = *(const float4*)&sAT[k][r0];
        float a[4] = {av.x, av.y, av.z, av.w};
        float b[12];
        #pragma unroll
        for (int co = 0; co < 3; co++) {
            float4 bv = *(const float4*)&sB[k][c0 + co*64];
            b[co*4+0] = bv.x; b[co*4+1] = bv.y; b[co*4+2] = bv.z; b[co*4+3] = bv.w;
        }
        #pragma unroll
        for (int ii = 0; ii < 4; ii++)
            #pragma unroll
            for (int jj = 0; jj < 12; jj++)
                acc[ii][jj] = fmaf(a[ii], b[jj], acc[ii][jj]);
    }
    #pragma unroll
    for (int ii = 0; ii < 4; ii++) {
        float* Cp = g_nodeT + (size_t)(rb + r0 + ii)*192;
        #pragma unroll
        for (int co = 0; co < 3; co++)
            *(float4*)(Cp + c0 + co*64) =
                make_float4(acc[ii][co*4+0], acc[ii][co*4+1], acc[ii][co*4+2], acc[ii][co*4+3]);
    }
}

// merged quad for both stages: bid<E1N/64 -> rel1, else rel0
__global__ void k_quadBoth(const float* __restrict__ rel1, const float* __restrict__ rel0) {
    __shared__ float sAT[64][72];
    __shared__ float sB[64][72];
    int bid = blockIdx.x;
    const float* rel; float* quadOut; int rb;
    if (bid < E1N/64) { rel = rel1; quadOut = g_quad1; rb = bid * 64; }
    else              { rel = rel0; quadOut = g_quad0; rb = (bid - E1N/64) * 64; }
    int t = threadIdx.x;
    int r = t >> 4, c4 = (t & 15) * 4;
    for (int rr = r; rr < 64; rr += 8) {
        float4 av = *(const float4*)(rel + (size_t)(rb + rr)*64 + c4);
        sAT[c4+0][rr] = av.x; sAT[c4+1][rr] = av.y;
        sAT[c4+2][rr] = av.z; sAT[c4+3][rr] = av.w;
    }
    for (int kk = r; kk < 64; kk += 8)
        *(float4*)&sB[kk][c4] = *(const float4*)(g_B2 + kk*64 + c4);
    __syncthreads();
    int tx = t & 15, ty = t >> 4;
    int r0 = ty * 8, c0 = tx * 4;
    float acc[8][4] = {};
    #pragma unroll 8
    for (int k = 0; k < 64; k++) {
        float4 a0 = *(const float4*)&sAT[k][r0];
        float4 a1 = *(const float4*)&sAT[k][r0+4];
        float4 bv = *(const float4*)&sB[k][c0];
        float a[8] = {a0.x, a0.y, a0.z, a0.w, a1.x, a1.y, a1.z, a1.w};
        float b[4] = {bv.x, bv.y, bv.z, bv.w};
        #pragma unroll
        for (int ii = 0; ii < 8; ii++)
            #pragma unroll
            for (int jj = 0; jj < 4; jj++)
                acc[ii][jj] = fmaf(a[ii], b[jj], acc[ii][jj]);
    }
    float qp[8];
    #pragma unroll
    for (int ii = 0; ii < 8; ii++) {
        float4 a = *(const float4*)(rel + (size_t)(rb + r0 + ii)*64 + c0);
        qp[ii] = acc[ii][0]*a.x + acc[ii][1]*a.y + acc[ii][2]*a.z + acc[ii][3]*a.w;
    }
    #pragma unroll
    for (int off = 8; off; off >>= 1)
        #pragma unroll
        for (int ii = 0; ii < 8; ii++)
            qp[ii] += __shfl_down_sync(~0u, qp[ii], off, 16);
    if (tx == 0) {
        #pragma unroll
        for (int ii = 0; ii < 8; ii++) quadOut[rb + r0 + ii] = qp[ii];
    }
}

// stage-1 logits
__global__ void k_logits1(const int* __restrict__ edges, const float* __restrict__ rel,
                          const float* __restrict__ H, const float* __restrict__ prior,
                          const float* __restrict__ gammaPtr) {
    __shared__ float sQ[192];
    __shared__ float sk0;
    int t = threadIdx.x;
    int q = blockIdx.x >> 3;
    if (t < 192) sQ[t] = g_QT[(size_t)q*320 + t];
    if (t == 192) sk0 = g_Qk0[q];
    __syncthreads();
    int w = blockIdx.x * 8 + (t >> 5);
    int lane = t & 31;
    int src = edges[w*8 + 6], dst = edges[w*8 + 7];
    const float2* hs  = (const float2*)(H + (size_t)src*64);
    const float2* hd  = (const float2*)(H + (size_t)dst*64);
    const float2* nts = (const float2*)(g_nodeT + (size_t)src*192);
    const float2* ntd = (const float2*)(g_nodeT + (size_t)dst*192);
    const float2* rp  = (const float2*)(rel + (size_t)w*64);
    float2 P  = nts[lane];
    float2 U  = nts[32 + lane];
    float2 Wd = ntd[64 + lane];
    float2 hdv = hd[lane], hsv = hs[lane], rv = rp[lane];
    float2 dq = ((const float2*)sQ)[lane];
    float2 cq = ((const float2*)(sQ + 64))[lane];
    float2 vq = ((const float2*)(sQ + 128))[lane];
    float acc = (P.x + dq.x) * hdv.x + (P.y + dq.y) * hdv.y;
    acc = fmaf(rv.x, (U.x + cq.x + Wd.x), acc);
    acc = fmaf(rv.y, (U.y + cq.y + Wd.y), acc);
    acc = fmaf(vq.x, hsv.x, acc);
    acc = fmaf(vq.y, hsv.y, acc);
    for (int o = 16; o; o >>= 1) acc += __shfl_xor_sync(~0u, acc, o);
    if (lane == 0) {
        float l = acc + sk0 + g_quad1[w];
        l = fmaf(gammaPtr[0], prior[w], l);
        g_logit[w] = l;
        g_esrc[w] = src; g_edst[w] = dst;
        atomicMax(&g_segmax[src], encf(l));
    }
}

// stage-0 logits (uses stage-0 seg buffers; H1 virtual)
__global__ void k_logits0(const int* __restrict__ edges, const float* __restrict__ rel,
                          const float* __restrict__ H, int nE) {
    int w = (blockIdx.x * blockDim.x + threadIdx.x) >> 5;
    int lane = threadIdx.x & 31;
    if (w >= nE) return;
    int q = edges[w*8 + 0], src = edges[w*8 + 6], dst = edges[w*8 + 7];
    const float* Hs = g_has[src] ? (const float*)g_H1 : H;
    const float* Hd = g_has[dst] ? (const float*)g_H1 : H;
    const float2* hs  = (const float2*)(Hs + (size_t)src*64);
    const float2* hd  = (const float2*)(Hd + (size_t)dst*64);
    const float2* nts = (const float2*)(g_nodeT + (size_t)src*192);
    const float2* ntd = (const float2*)(g_nodeT + (size_t)dst*192);
    const float2* rp  = (const float2*)(rel + (size_t)w*64);
    const float2* qd  = (const float2*)(g_QT + (size_t)q*320);
    const float2* qc  = (const float2*)(g_QT + (size_t)q*320 + 64);
    const float2* qv  = (const float2*)(g_QT + (size_t)q*320 + 128);
    float2 P  = nts[lane];
    float2 U  = nts[32 + lane];
    float2 Wd = ntd[64 + lane];
    float2 hdv = hd[lane], hsv = hs[lane], rv = rp[lane];
    float2 dq = qd[lane], cq = qc[lane], vq = qv[lane];
    float acc = (P.x + dq.x) * hdv.x + (P.y + dq.y) * hdv.y;
    acc = fmaf(rv.x, (U.x + cq.x + Wd.x), acc);
    acc = fmaf(rv.y, (U.y + cq.y + Wd.y), acc);
    acc = fmaf(vq.x, hsv.x, acc);
    acc = fmaf(vq.y, hsv.y, acc);
    for (int o = 16; o; o >>= 1) acc += __shfl_xor_sync(~0u, acc, o);
    if (lane == 0) {
        float l = acc + g_Qk0[q] + g_quad0[w];
        g_logit[w] = l;
        g_esrc[w] = src; g_edst[w] = dst;
        atomicMax(&g_segmax0[src], encf(l));
    }
}

// exp + segment sum (stage selectable buffers)
__global__ void k_pass2(int stage0, int nE) {
    int e = blockIdx.x * blockDim.x + threadIdx.x;
    if (e >= nE) return;
    int src = g_esrc[e];
    if (!stage0) {
        float mx = decf(g_segmax[src]);
        float v = expf(g_logit[e] - mx);
        g_logit[e] = v;
        atomicAdd(&g_segsum[src], v);
    } else {
        float mx = decf(g_segmax0[src]);
        float v = expf(g_logit[e] - mx);
        g_logit[e] = v;
        atomicAdd(&g_segsum0[src], v);
        g_has0[src] = 1;
    }
}

// top-10 of 64 per query; builds chg list + zeroes H1 rows on first-set
__global__ void k_topk(const int* __restrict__ edges1, const float* __restrict__ score,
                       float* __restrict__ out) {
    int w = (blockIdx.x * blockDim.x + threadIdx.x) >> 5;
    int lane = threadIdx.x & 31;
    if (w >= NQ) return;
    int g0 = lane, g1 = lane + 32;
    int e0 = w*64 + g0, e1 = w*64 + g1;
    int s0 = g_esrc[e0], s1 = g_esrc[e1];
    float tr0 = g_logit[e0] / g_segsum[s0];
    float tr1 = g_logit[e1] / g_segsum[s1];
    float v0 = tr0 * score[s0];
    float v1 = tr1 * score[s1];
    int myG = 0; float myTr = 0.f;
    for (int k = 0; k < KSEL; k++) {
        float bv; int bg; float bt;
        if (v0 >= v1) { bv = v0; bg = g0; bt = tr0; }
        else          { bv = v1; bg = g1; bt = tr1; }
        for (int o = 16; o; o >>= 1) {
            float ov = __shfl_xor_sync(~0u, bv, o);
            int   og = __shfl_xor_sync(~0u, bg, o);
            float ot = __shfl_xor_sync(~0u, bt, o);
            if (ov > bv || (ov == bv && og < bg)) { bv = ov; bg = og; bt = ot; }
        }
        if (lane == k) { myG = bg; myTr = bt; }
        if (g0 == bg) v0 = -__int_as_float(0x7f800000);
        if (g1 == bg) v1 = -__int_as_float(0x7f800000);
    }
    if (lane < KSEL) {
        int orig = w*64 + myG;
        int oi = w*KSEL + lane;
        int src = g_esrc[orig], dst = g_edst[orig];
        g_psrc[oi] = src; g_pdst[oi] = dst; g_ptrans[oi] = myTr;
        if (atomicExch(&g_has[src], 1) == 0) {
            int idx = atomicAdd(&g_ncnt, 1);
            g_chg[idx] = src;
            float4* hp = (float4*)(g_H1 + (size_t)src*64);
            #pragma unroll
            for (int c = 0; c < 16; c++) hp[c] = make_float4(0.f, 0.f, 0.f, 0.f);
        }
        atomicAdd(out + dst, myTr * score[src]);
        float* pe = out + OFF_PE + (size_t)oi*8;
        for (int c = 0; c < 8; c++) pe[c] = (float)edges1[orig*8 + c];
        out[OFF_OI + oi] = (float)orig;
    }
}

// pruned-edge scatter: H1[src] += trans * H[dst]
__global__ void k_scatter1(const float* __restrict__ H) {
    int w = (blockIdx.x * blockDim.x + threadIdx.x) >> 5;
    int lane = threadIdx.x & 31;
    if (w >= NQ*KSEL) return;
    int src = g_psrc[w], dst = g_pdst[w];
    float t = g_ptrans[w];
    float2 hv = ((const float2*)(H + (size_t)dst*64))[lane];
    atomicAdd(&g_H1[(size_t)src*64 + 2*lane + 0], t * hv.x);
    atomicAdd(&g_H1[(size_t)src*64 + 2*lane + 1], t * hv.y);
}

// delta nodeT update over changed list
__global__ void k_dgemm(const float* __restrict__ Hold) {
    int cnt = g_ncnt;
    int rb = blockIdx.x * 64;
    if (rb >= cnt) return;
    __shared__ float sAT[64][72];
    __shared__ float sB[64][72];
    __shared__ int snode[64];
    int t = threadIdx.x;
    int cb = blockIdx.y * 64;
    if (t < 64) snode[t] = (rb + t < cnt) ? g_chg[rb + t] : -1;
    __syncthreads();
    int r = t >> 4, c4 = (t & 15) * 4;
    for (int rr = r; rr < 64; rr += 16) {
        int node = snode[rr];
        float4 av = make_float4(0.f, 0.f, 0.f, 0.f);
        if (node >= 0) {
            float4 a = *(const float4*)(g_H1 + (size_t)node*64 + c4);
            float4 b = *(const float4*)(Hold + (size_t)node*64 + c4);
            av = make_float4(a.x - b.x, a.y - b.y, a.z - b.z, a.w - b.w);
        }
        sAT[c4+0][rr] = av.x; sAT[c4+1][rr] = av.y;
        sAT[c4+2][rr] = av.z; sAT[c4+3][rr] = av.w;
    }
    for (int kk = r; kk < 64; kk += 16)
        *(float4*)&sB[kk][c4] = *(const float4*)(g_B1 + kk*192 + cb + c4);
    __syncthreads();
    int tx = t & 15, ty = t >> 4;
    int r0 = ty * 4, c0 = tx * 4;
    float acc[4][4] = {};
    #pragma unroll 8
    for (int k = 0; k < 64; k++) {
        float4 av = *(const float4*)&sAT[k][r0];
        float4 bv = *(const float4*)&sB[k][c0];
        float a[4] = {av.x, av.y, av.z, av.w};
        float b[4] = {bv.x, bv.y, bv.z, bv.w};
        #pragma unroll
        for (int ii = 0; ii < 4; ii++)
            #pragma unroll
            for (int jj = 0; jj < 4; jj++)
                acc[ii][jj] = fmaf(a[ii], b[jj], acc[ii][jj]);
    }
    #pragma unroll
    for (int ii = 0; ii < 4; ii++) {
        int node = snode[r0 + ii];
        if (node < 0) continue;
        float* Cp = g_nodeT + (size_t)node*192 + cb + c0;
        float4 co = *(const float4*)Cp;
        co.x += acc[ii][0]; co.y += acc[ii][1]; co.z += acc[ii][2]; co.w += acc[ii][3];
        *(float4*)Cp = co;
    }
}

// zero H2 rows for has0 nodes (scatter0 targets exactly these rows)
__global__ void k_zero0() {
    int i = blockIdx.x * blockDim.x + threadIdx.x;
    if (i >= N_NODES * 16) return;
    if (g_has0[i >> 4]) ((float4*)g_H2)[i] = make_float4(0.f, 0.f, 0.f, 0.f);
}

// edges0 scatter: H2[src] += trans0 * H1virtual[dst]
__global__ void k_scatter0(const float* __restrict__ H) {
    int w = (blockIdx.x * blockDim.x + threadIdx.x) >> 5;
    int lane = threadIdx.x & 31;
    if (w >= E0N) return;
    int src = g_esrc[w], dst = g_edst[w];
    float t = g_logit[w] / g_segsum0[src];
    const float* Hd = g_has[dst] ? (const float*)g_H1 : H;
    float2 hv = ((const float2*)(Hd + (size_t)dst*64))[lane];
    atomicAdd(&g_H2[(size_t)src*64 + 2*lane + 0], t * hv.x);
    atomicAdd(&g_H2[(size_t)src*64 + 2*lane + 1], t * hv.y);
}

// final: out = leaky(Hv @ BL + b); per-row A select has0?H2:(has?H1:H)
__global__ void k_gemmF(const float* __restrict__ H, float* __restrict__ C,
                        const float* __restrict__ bias) {
    __shared__ float sAT[64][72];
    __shared__ float sB[64][72];
    int t = threadIdx.x;
    int rb = blockIdx.x * 64;
    int r = t >> 4, c4 = (t & 15) * 4;
    for (int rr = r; rr < 64; rr += 8) {
        int node = rb + rr;
        const float* Ap = g_has0[node] ? (const float*)g_H2
                         : (g_has[node] ? (const float*)g_H1 : H);
        float4 av = *(const float4*)(Ap + (size_t)node*64 + c4);
        sAT[c4+0][rr] = av.x; sAT[c4+1][rr] = av.y;
        sAT[c4+2][rr] = av.z; sAT[c4+3][rr] = av.w;
    }
    for (int kk = r; kk < 64; kk += 8)
        *(float4*)&sB[kk][c4] = *(const float4*)(g_BL + kk*64 + c4);
    __syncthreads();
    int tx = t & 15, ty = t >> 4;
    int r0 = ty * 8, c0 = tx * 4;
    float acc[8][4] = {};
    #pragma unroll 8
    for (int k = 0; k < 64; k++) {
        float4 a0 = *(const float4*)&sAT[k][r0];
        float4 a1 = *(const float4*)&sAT[k][r0+4];
        float4 bv = *(const float4*)&sB[k][c0];
        float a[8] = {a0.x, a0.y, a0.z, a0.w, a1.x, a1.y, a1.z, a1.w};
        float b[4] = {bv.x, bv.y, bv.z, bv.w};
        #pragma unroll
        for (int ii = 0; ii < 8; ii++)
            #pragma unroll
            for (int jj = 0; jj < 4; jj++)
                acc[ii][jj] = fmaf(a[ii], b[jj], acc[ii][jj]);
    }
    #pragma unroll
    for (int ii = 0; ii < 8; ii++) {
        float4 o = make_float4(acc[ii][0], acc[ii][1], acc[ii][2], acc[ii][3]);
        o.x += bias[c0 + 0]; o.y += bias[c0 + 1];
        o.z += bias[c0 + 2]; o.w += bias[c0 + 3];
        o.x = o.x >= 0.f ? o.x : 0.01f * o.x;
        o.y = o.y >= 0.f ? o.y : 0.01f * o.y;
        o.z = o.z >= 0.f ? o.z : 0.01f * o.z;
        o.w = o.w >= 0.f ? o.w : 0.01f * o.w;
        *(float4*)(C + (size_t)(rb + r0 + ii)*64 + c0) = o;
    }
}

// ---------------- launch ----------------
extern "C" void kernel_launch(void* const* d_in, const int* in_sizes, int n_in,
                              void* d_out, int out_size) {
    const float* score = (const float*)d_in[0];
    const float* H     = (const float*)d_in[1];
    const float* rel0  = (const float*)d_in[2];
    const float* rel1  = (const float*)d_in[3];
    const float* prior = (const float*)d_in[4];
    const float* qst   = (const float*)d_in[5];
    const float* qrl   = (const float*)d_in[6];
    const float* Wq    = (const float*)d_in[7];
    const float* Wk    = (const float*)d_in[8];
    const float* Wlin  = (const float*)d_in[9];
    const float* blin  = (const float*)d_in[10];
    const float* gamma = (const float*)d_in[11];
    const int*   e0    = (const int*)d_in[12];
    const int*   e1    = (const int*)d_in[13];
    float* out = (float*)d_out;

    static int smemSet = 0;
    const int NSMEM = (64*68 + 64*196) * 4;   // 67584 B
    cudaFuncSetAttribute(k_gemmN, cudaFuncAttributeMaxDynamicSharedMemorySize, NSMEM);
    (void)smemSet;

    k_init1<<<(N_NODES + 255)/256, 256>>>(out);
    k_gemmM<<<dim3(8, 4), 128>>>(Wq, Wk);
    k_buildB<<<(64*192 + 2*64*64 + 128*320 + 255)/256, 256>>>(Wlin);
    k_packQA<<<NQ*128/256, 256>>>(qst, qrl);
    k_gemmQ<<<dim3(NQ/64, 5), 128>>>();
    k_qk0<<<NQ*32/256, 256>>>();

    // ---- stage 1 ----
    k_gemmN<<<N_NODES/64, 256, NSMEM>>>(H);
    k_quadBoth<<<(E1N + E0N)/64, 128>>>(rel1, rel0);
    k_logits1<<<E1N/8, 256>>>(e1, rel1, H, prior, gamma);
    k_pass2<<<E1N/256, 256>>>(0, E1N);
    k_topk<<<NQ/8, 256>>>(e1, score, out);
    k_scatter1<<<(NQ*KSEL)/8, 256>>>(H);

    // ---- stage 0 ----
    k_dgemm<<<dim3((NQ*KSEL)/64, 3), 256>>>(H);
    k_logits0<<<E0N/8, 256>>>(e0, rel0, H, E0N);
    k_pass2<<<E0N/256, 256>>>(1, E0N);
    k_zero0<<<(N_NODES*16 + 255)/256, 256>>>();
    k_scatter0<<<E0N/8, 256>>>(H);

    // ---- final ----
    k_gemmF<<<N_NODES/64, 128>>>(H, out + OFF_REPR, blin);
}

// round 6
// speedup vs baseline: 1.1913x; 1.0187x over previous
#include <cuda_runtime.h>
#include <cstdint>

#define N_NODES 200000
#define DIM 64
#define NQ 4096
#define E1N 262144
#define E0N 131072
#define KSEL 10

#define OFF_REPR  (N_NODES)
#define OFF_PE    (N_NODES + N_NODES*DIM)
#define OFF_OI    (OFF_PE + NQ*KSEL*8)

#define NBI   ((N_NODES + 255)/256)     // 782 init blocks
#define NB_N  (N_NODES/64)              // 3125
#define NB_QT ((NQ/64)*5)               // 320
#define NB_QD ((E1N + E0N)/64)          // 6144

// ---------------- scratch ----------------
__device__ float    g_M [256*256];
__device__ float    g_B1[64*192];
__device__ float    g_B2[64*64];
__device__ float    g_BL[64*64];
__device__ float    g_Bq[128*320];
__device__ float    g_QT[(size_t)NQ*320];
__device__ float    g_Qk0[NQ];
__device__ float    g_nodeT[(size_t)N_NODES*192];
__device__ float    g_quad1[E1N];
__device__ float    g_quad0[E0N];
__device__ float    g_logit[E1N];
__device__ int      g_esrc[E1N];
__device__ int      g_edst[E1N];
__device__ unsigned g_segmax [N_NODES];
__device__ float    g_segsum [N_NODES];
__device__ unsigned g_segmax0[N_NODES];
__device__ float    g_segsum0[N_NODES];
__device__ int      g_has [N_NODES];
__device__ int      g_has0[N_NODES];
__device__ float    g_H1[(size_t)N_NODES*DIM];
__device__ float    g_H2[(size_t)N_NODES*DIM];
__device__ int      g_psrc[NQ*KSEL];
__device__ int      g_pdst[NQ*KSEL];
__device__ float    g_ptrans[NQ*KSEL];
__device__ int      g_chg[NQ*KSEL];
__device__ int      g_ncnt;

__device__ __forceinline__ unsigned encf(float f) {
    unsigned u = __float_as_uint(f);
    return (u & 0x80000000u) ? ~u : (u | 0x80000000u);
}
__device__ __forceinline__ float decf(unsigned u) {
    return (u & 0x80000000u) ? __uint_as_float(u & 0x7fffffffu) : __uint_as_float(~u);
}

// ---------------- launch A: init ∥ M = Wq^T @ Wk ----------------
__global__ void k_prep(float* __restrict__ outScore,
                       const float* __restrict__ Wq, const float* __restrict__ Wk) {
    __shared__ float sA[64][36];
    __shared__ float sB[64][72];
    int t = threadIdx.x;
    if (blockIdx.x < NBI) {
        int i = blockIdx.x * 256 + t;
        if (i < N_NODES) {
            g_segmax[i] = 0u;  g_segsum[i] = 0.f;
            g_segmax0[i] = 0u; g_segsum0[i] = 0.f;
            g_has[i] = 0; g_has0[i] = 0;
            outScore[i] = 0.f;
        }
        if (i < NQ) g_Qk0[i] = 0.f;
        if (i == 0) g_ncnt = 0;
        return;
    }
    // gemmM: 32x64 tile, 256 threads, acc[2][4]
    int b = blockIdx.x - NBI;              // 0..31
    int ib = (b & 7) * 32, jb = (b >> 3) * 64;
    int tx = t & 15, ty = t >> 4;
    int r0 = ty * 2, c0 = tx * 4;
    float acc[2][4] = {};
    for (int kc = 0; kc < 256; kc += 64) {
        __syncthreads();
        {
            int ra = t >> 3, ca = (t & 7) * 4;
            for (int kk = ra; kk < 64; kk += 32)
                *(float4*)&sA[kk][ca] = *(const float4*)(Wq + (size_t)(kc + kk)*256 + ib + ca);
            int rbb = t >> 4, cbb = (t & 15) * 4;
            for (int kk = rbb; kk < 64; kk += 16)
                *(float4*)&sB[kk][cbb] = *(const float4*)(Wk + (size_t)(kc + kk)*256 + jb + cbb);
        }
        __syncthreads();
        #pragma unroll 8
        for (int k = 0; k < 64; k++) {
            float2 av = *(const float2*)&sA[k][r0];
            float4 bv = *(const float4*)&sB[k][c0];
            float a[2] = {av.x, av.y};
            float bb[4] = {bv.x, bv.y, bv.z, bv.w};
            #pragma unroll
            for (int ii = 0; ii < 2; ii++)
                #pragma unroll
                for (int jj = 0; jj < 4; jj++)
                    acc[ii][jj] = fmaf(a[ii], bb[jj], acc[ii][jj]);
        }
    }
    #pragma unroll
    for (int ii = 0; ii < 2; ii++)
        *(float4*)(g_M + (size_t)(ib + r0 + ii)*256 + jb + c0) =
            make_float4(acc[ii][0], acc[ii][1], acc[ii][2], acc[ii][3]);
}

__global__ void k_buildB(const float* __restrict__ W_lin) {
    int t = blockIdx.x * blockDim.x + threadIdx.x;
    if (t < 64*192) {
        int k = t / 192, c = t % 192;
        float v;
        if (c < 128) v = g_M[k*256 + c];
        else         v = g_M[(64 + (c-128))*256 + k];
        g_B1[t] = v;
    } else if (t < 64*192 + 64*64) {
        int t2 = t - 64*192; int k = t2 / 64, i = t2 % 64;
        g_B2[t2] = g_M[(64+i)*256 + (64+k)];
    } else if (t < 64*192 + 2*64*64) {
        int t3 = t - 64*192 - 64*64; int k = t3 / 64, i = t3 % 64;
        g_BL[t3] = W_lin[i*64 + k];
    } else if (t < 64*192 + 2*64*64 + 128*320) {
        int t4 = t - 64*192 - 2*64*64;
        int k = t4 / 320, c = t4 % 320;
        float v;
        if      (c < 64)  v = g_M[(128+k)*256 + c];
        else if (c < 128) v = g_M[(128+k)*256 + c] + g_M[c*256 + 128 + k];
        else if (c < 192) v = g_M[(c-128)*256 + 128 + k];
        else              v = g_M[(c-64)*256 + 128 + k];
        g_Bq[t4] = v;
    }
}

// ---------------- launch B: gemmN ∥ gemmQ(+k0) ∥ quadBoth ----------------
extern __shared__ float smU[];

__device__ void gemmN_body(int bidN, const float* __restrict__ A) {
    float (*sAT)[68] = (float(*)[68])smU;
    float (*sB)[196] = (float(*)[196])(smU + 64*68);
    int t = threadIdx.x;
    int rb = bidN * 64;
    {
        int r = t >> 4, c4 = (t & 15) * 4;
        for (int rr = r; rr < 64; rr += 16) {
            float4 av = *(const float4*)(A + (size_t)(rb + rr)*64 + c4);
            sAT[c4+0][rr] = av.x; sAT[c4+1][rr] = av.y;
            sAT[c4+2][rr] = av.z; sAT[c4+3][rr] = av.w;
        }
        for (int kk = r; kk < 64; kk += 16) {
            #pragma unroll
            for (int co = 0; co < 3; co++)
                *(float4*)&sB[kk][c4 + co*64] = *(const float4*)(g_B1 + (size_t)kk*192 + c4 + co*64);
        }
    }
    __syncthreads();
    int tx = t & 15, ty = t >> 4;
    int r0 = ty * 4, c0 = tx * 4;
    float acc[4][12] = {};
    #pragma unroll 4
    for (int k = 0; k < 64; k++) {
        float4 av = *(const float4*)&sAT[k][r0];
        float a[4] = {av.x, av.y, av.z, av.w};
        float b[12];
        #pragma unroll
        for (int co = 0; co < 3; co++) {
            float4 bv = *(const float4*)&sB[k][c0 + co*64];
            b[co*4+0] = bv.x; b[co*4+1] = bv.y; b[co*4+2] = bv.z; b[co*4+3] = bv.w;
        }
        #pragma unroll
        for (int ii = 0; ii < 4; ii++)
            #pragma unroll
            for (int jj = 0; jj < 12; jj++)
                acc[ii][jj] = fmaf(a[ii], b[jj], acc[ii][jj]);
    }
    #pragma unroll
    for (int ii = 0; ii < 4; ii++) {
        float* Cp = g_nodeT + (size_t)(rb + r0 + ii)*192;
        #pragma unroll
        for (int co = 0; co < 3; co++)
            *(float4*)(Cp + c0 + co*64) =
                make_float4(acc[ii][co*4+0], acc[ii][co*4+1], acc[ii][co*4+2], acc[ii][co*4+3]);
    }
}

__device__ void gemmQ_body(int b, const float* __restrict__ qst, const float* __restrict__ qrl) {
    float (*sAT)[72] = (float(*)[72])smU;
    float (*sB)[72]  = (float(*)[72])(smU + 64*72);
    int t = threadIdx.x;
    int rb = (b & 63) * 64, cb = (b >> 6) * 64;
    int tx = t & 15, ty = t >> 4;
    int r0 = ty * 4, c0 = tx * 4;
    float acc[4][4] = {};
    for (int kc = 0; kc < 128; kc += 64) {
        __syncthreads();
        {
            const float* Qsrc = (kc == 0) ? qst : qrl;
            int r = t >> 4, c4 = (t & 15) * 4;
            for (int rr = r; rr < 64; rr += 16) {
                float4 av = *(const float4*)(Qsrc + (size_t)(rb + rr)*64 + c4);
                sAT[c4+0][rr] = av.x; sAT[c4+1][rr] = av.y;
                sAT[c4+2][rr] = av.z; sAT[c4+3][rr] = av.w;
            }
            for (int kk = r; kk < 64; kk += 16)
                *(float4*)&sB[kk][c4] = *(const float4*)(g_Bq + (size_t)(kc + kk)*320 + cb + c4);
        }
        __syncthreads();
        #pragma unroll 8
        for (int k = 0; k < 64; k++) {
            float4 av = *(const float4*)&sAT[k][r0];
            float4 bv = *(const float4*)&sB[k][c0];
            float a[4] = {av.x, av.y, av.z, av.w};
            float bb[4] = {bv.x, bv.y, bv.z, bv.w};
            #pragma unroll
            for (int ii = 0; ii < 4; ii++)
                #pragma unroll
                for (int jj = 0; jj < 4; jj++)
                    acc[ii][jj] = fmaf(a[ii], bb[jj], acc[ii][jj]);
        }
    }
    if (cb < 192) {
        #pragma unroll
        for (int ii = 0; ii < 4; ii++)
            *(float4*)(g_QT + (size_t)(rb + r0 + ii)*320 + cb + c0) =
                make_float4(acc[ii][0], acc[ii][1], acc[ii][2], acc[ii][3]);
    } else {
        // k0 partial: dot rows of this QT block against QA columns
        const float* Qsrc2 = (cb == 192) ? qst : qrl;
        float qp[4];
        #pragma unroll
        for (int ii = 0; ii < 4; ii++) {
            float4 a = *(const float4*)(Qsrc2 + (size_t)(rb + r0 + ii)*64 + c0);
            qp[ii] = acc[ii][0]*a.x + acc[ii][1]*a.y + acc[ii][2]*a.z + acc[ii][3]*a.w;
        }
        #pragma unroll
        for (int off = 8; off; off >>= 1)
            #pragma unroll
            for (int ii = 0; ii < 4; ii++)
                qp[ii] += __shfl_down_sync(~0u, qp[ii], off, 16);
        if (tx == 0) {
            #pragma unroll
            for (int ii = 0; ii < 4; ii++)
                atomicAdd(&g_Qk0[rb + r0 + ii], qp[ii]);
        }
    }
}

__device__ void quad_body(int b, const float* __restrict__ rel1, const float* __restrict__ rel0) {
    const float* rel; float* quadOut; int rb;
    if (b < E1N/64) { rel = rel1; quadOut = g_quad1; rb = b * 64; }
    else            { rel = rel0; quadOut = g_quad0; rb = (b - E1N/64) * 64; }
    float (*sAT)[72] = (float(*)[72])smU;
    float (*sB)[72]  = (float(*)[72])(smU + 64*72);
    int t = threadIdx.x;
    int r = t >> 4, c4 = (t & 15) * 4;
    for (int rr = r; rr < 64; rr += 16) {
        float4 av = *(const float4*)(rel + (size_t)(rb + rr)*64 + c4);
        sAT[c4+0][rr] = av.x; sAT[c4+1][rr] = av.y;
        sAT[c4+2][rr] = av.z; sAT[c4+3][rr] = av.w;
    }
    for (int kk = r; kk < 64; kk += 16)
        *(float4*)&sB[kk][c4] = *(const float4*)(g_B2 + kk*64 + c4);
    __syncthreads();
    int tx = t & 15, ty = t >> 4;
    int r0 = ty * 4, c0 = tx * 4;
    float acc[4][4] = {};
    #pragma unroll 8
    for (int k = 0; k < 64; k++) {
        float4 av = *(const float4*)&sAT[k][r0];
        float4 bv = *(const float4*)&sB[k][c0];
        float a[4] = {av.x, av.y, av.z, av.w};
        float bb[4] = {bv.x, bv.y, bv.z, bv.w};
        #pragma unroll
        for (int ii = 0; ii < 4; ii++)
            #pragma unroll
            for (int jj = 0; jj < 4; jj++)
                acc[ii][jj] = fmaf(a[ii], bb[jj], acc[ii][jj]);
    }
    float qp[4];
    #pragma unroll
    for (int ii = 0; ii < 4; ii++) {
        float4 a = *(const float4*)(rel + (size_t)(rb + r0 + ii)*64 + c0);
        qp[ii] = acc[ii][0]*a.x + acc[ii][1]*a.y + acc[ii][2]*a.z + acc[ii][3]*a.w;
    }
    #pragma unroll
    for (int off = 8; off; off >>= 1)
        #pragma unroll
        for (int ii = 0; ii < 4; ii++)
            qp[ii] += __shfl_down_sync(~0u, qp[ii], off, 16);
    if (tx == 0) {
        #pragma unroll
        for (int ii = 0; ii < 4; ii++) quadOut[rb + r0 + ii] = qp[ii];
    }
}

__global__ void k_uberB(const float* __restrict__ H,
                        const float* __restrict__ rel1, const float* __restrict__ rel0,
                        const float* __restrict__ qst,  const float* __restrict__ qrl) {
    int bid = blockIdx.x;
    if (bid < NB_N)             gemmN_body(bid, H);
    else if (bid < NB_N + NB_QT) gemmQ_body(bid - NB_N, qst, qrl);
    else                         quad_body(bid - NB_N - NB_QT, rel1, rel0);
}

// ---------------- logits ----------------
__global__ void k_logits1(const int* __restrict__ edges, const float* __restrict__ rel,
                          const float* __restrict__ H, const float* __restrict__ prior,
                          const float* __restrict__ gammaPtr) {
    __shared__ float sQ[192];
    __shared__ float sk0;
    int t = threadIdx.x;
    int q = blockIdx.x >> 3;
    if (t < 192) sQ[t] = g_QT[(size_t)q*320 + t];
    if (t == 192) sk0 = g_Qk0[q];
    __syncthreads();
    int w = blockIdx.x * 8 + (t >> 5);
    int lane = t & 31;
    int src = edges[w*8 + 6], dst = edges[w*8 + 7];
    const float2* hs  = (const float2*)(H + (size_t)src*64);
    const float2* hd  = (const float2*)(H + (size_t)dst*64);
    const float2* nts = (const float2*)(g_nodeT + (size_t)src*192);
    const float2* ntd = (const float2*)(g_nodeT + (size_t)dst*192);
    const float2* rp  = (const float2*)(rel + (size_t)w*64);
    float2 P  = nts[lane];
    float2 U  = nts[32 + lane];
    float2 Wd = ntd[64 + lane];
    float2 hdv = hd[lane], hsv = hs[lane], rv = rp[lane];
    float2 dq = ((const float2*)sQ)[lane];
    float2 cq = ((const float2*)(sQ + 64))[lane];
    float2 vq = ((const float2*)(sQ + 128))[lane];
    float acc = (P.x + dq.x) * hdv.x + (P.y + dq.y) * hdv.y;
    acc = fmaf(rv.x, (U.x + cq.x + Wd.x), acc);
    acc = fmaf(rv.y, (U.y + cq.y + Wd.y), acc);
    acc = fmaf(vq.x, hsv.x, acc);
    acc = fmaf(vq.y, hsv.y, acc);
    for (int o = 16; o; o >>= 1) acc += __shfl_xor_sync(~0u, acc, o);
    if (lane == 0) {
        float l = acc + sk0 + g_quad1[w];
        l = fmaf(gammaPtr[0], prior[w], l);
        g_logit[w] = l;
        g_esrc[w] = src; g_edst[w] = dst;
        atomicMax(&g_segmax[src], encf(l));
    }
}

__global__ void k_logits0(const int* __restrict__ edges, const float* __restrict__ rel,
                          const float* __restrict__ H, int nE) {
    int w = (blockIdx.x * blockDim.x + threadIdx.x) >> 5;
    int lane = threadIdx.x & 31;
    if (w >= nE) return;
    int q = edges[w*8 + 0], src = edges[w*8 + 6], dst = edges[w*8 + 7];
    const float* Hs = g_has[src] ? (const float*)g_H1 : H;
    const float* Hd = g_has[dst] ? (const float*)g_H1 : H;
    const float2* hs  = (const float2*)(Hs + (size_t)src*64);
    const float2* hd  = (const float2*)(Hd + (size_t)dst*64);
    const float2* nts = (const float2*)(g_nodeT + (size_t)src*192);
    const float2* ntd = (const float2*)(g_nodeT + (size_t)dst*192);
    const float2* rp  = (const float2*)(rel + (size_t)w*64);
    const float2* qd  = (const float2*)(g_QT + (size_t)q*320);
    const float2* qc  = (const float2*)(g_QT + (size_t)q*320 + 64);
    const float2* qv  = (const float2*)(g_QT + (size_t)q*320 + 128);
    float2 P  = nts[lane];
    float2 U  = nts[32 + lane];
    float2 Wd = ntd[64 + lane];
    float2 hdv = hd[lane], hsv = hs[lane], rv = rp[lane];
    float2 dq = qd[lane], cq = qc[lane], vq = qv[lane];
    float acc = (P.x + dq.x) * hdv.x + (P.y + dq.y) * hdv.y;
    acc = fmaf(rv.x, (U.x + cq.x + Wd.x), acc);
    acc = fmaf(rv.y, (U.y + cq.y + Wd.y), acc);
    acc = fmaf(vq.x, hsv.x, acc);
    acc = fmaf(vq.y, hsv.y, acc);
    for (int o = 16; o; o >>= 1) acc += __shfl_xor_sync(~0u, acc, o);
    if (lane == 0) {
        float l = acc + g_Qk0[q] + g_quad0[w];
        g_logit[w] = l;
        g_esrc[w] = src; g_edst[w] = dst;
        atomicMax(&g_segmax0[src], encf(l));
    }
}

// exp + segment sum; stage0 also zeroes H2 row on first-set of has0
__global__ void k_pass2(int stage0, int nE) {
    int e = blockIdx.x * blockDim.x + threadIdx.x;
    if (e >= nE) return;
    int src = g_esrc[e];
    if (!stage0) {
        float mx = decf(g_segmax[src]);
        float v = expf(g_logit[e] - mx);
        g_logit[e] = v;
        atomicAdd(&g_segsum[src], v);
    } else {
        float mx = decf(g_segmax0[src]);
        float v = expf(g_logit[e] - mx);
        g_logit[e] = v;
        atomicAdd(&g_segsum0[src], v);
        if (atomicExch(&g_has0[src], 1) == 0) {
            float4* hp = (float4*)(g_H2 + (size_t)src*64);
            #pragma unroll
            for (int c = 0; c < 16; c++) hp[c] = make_float4(0.f, 0.f, 0.f, 0.f);
        }
    }
}

// top-10 of 64 per query; builds chg list + zeroes H1 rows on first-set
__global__ void k_topk(const int* __restrict__ edges1, const float* __restrict__ score,
                       float* __restrict__ out) {
    int w = (blockIdx.x * blockDim.x + threadIdx.x) >> 5;
    int lane = threadIdx.x & 31;
    if (w >= NQ) return;
    int g0 = lane, g1 = lane + 32;
    int e0 = w*64 + g0, e1 = w*64 + g1;
    int s0 = g_esrc[e0], s1 = g_esrc[e1];
    float tr0 = g_logit[e0] / g_segsum[s0];
    float tr1 = g_logit[e1] / g_segsum[s1];
    float v0 = tr0 * score[s0];
    float v1 = tr1 * score[s1];
    int myG = 0; float myTr = 0.f;
    for (int k = 0; k < KSEL; k++) {
        float bv; int bg; float bt;
        if (v0 >= v1) { bv = v0; bg = g0; bt = tr0; }
        else          { bv = v1; bg = g1; bt = tr1; }
        for (int o = 16; o; o >>= 1) {
            float ov = __shfl_xor_sync(~0u, bv, o);
            int   og = __shfl_xor_sync(~0u, bg, o);
            float ot = __shfl_xor_sync(~0u, bt, o);
            if (ov > bv || (ov == bv && og < bg)) { bv = ov; bg = og; bt = ot; }
        }
        if (lane == k) { myG = bg; myTr = bt; }
        if (g0 == bg) v0 = -__int_as_float(0x7f800000);
        if (g1 == bg) v1 = -__int_as_float(0x7f800000);
    }
    if (lane < KSEL) {
        int orig = w*64 + myG;
        int oi = w*KSEL + lane;
        int src = g_esrc[orig], dst = g_edst[orig];
        g_psrc[oi] = src; g_pdst[oi] = dst; g_ptrans[oi] = myTr;
        if (atomicExch(&g_has[src], 1) == 0) {
            int idx = atomicAdd(&g_ncnt, 1);
            g_chg[idx] = src;
            float4* hp = (float4*)(g_H1 + (size_t)src*64);
            #pragma unroll
            for (int c = 0; c < 16; c++) hp[c] = make_float4(0.f, 0.f, 0.f, 0.f);
        }
        atomicAdd(out + dst, myTr * score[src]);
        float* pe = out + OFF_PE + (size_t)oi*8;
        for (int c = 0; c < 8; c++) pe[c] = (float)edges1[orig*8 + c];
        out[OFF_OI + oi] = (float)orig;
    }
}

__global__ void k_scatter1(const float* __restrict__ H) {
    int w = (blockIdx.x * blockDim.x + threadIdx.x) >> 5;
    int lane = threadIdx.x & 31;
    if (w >= NQ*KSEL) return;
    int src = g_psrc[w], dst = g_pdst[w];
    float t = g_ptrans[w];
    float2 hv = ((const float2*)(H + (size_t)dst*64))[lane];
    atomicAdd(&g_H1[(size_t)src*64 + 2*lane + 0], t * hv.x);
    atomicAdd(&g_H1[(size_t)src*64 + 2*lane + 1], t * hv.y);
}

__global__ void k_dgemm(const float* __restrict__ Hold) {
    int cnt = g_ncnt;
    int rb = blockIdx.x * 64;
    if (rb >= cnt) return;
    __shared__ float sAT[64][72];
    __shared__ float sB[64][72];
    __shared__ int snode[64];
    int t = threadIdx.x;
    int cb = blockIdx.y * 64;
    if (t < 64) snode[t] = (rb + t < cnt) ? g_chg[rb + t] : -1;
    __syncthreads();
    int r = t >> 4, c4 = (t & 15) * 4;
    for (int rr = r; rr < 64; rr += 16) {
        int node = snode[rr];
        float4 av = make_float4(0.f, 0.f, 0.f, 0.f);
        if (node >= 0) {
            float4 a = *(const float4*)(g_H1 + (size_t)node*64 + c4);
            float4 b = *(const float4*)(Hold + (size_t)node*64 + c4);
            av = make_float4(a.x - b.x, a.y - b.y, a.z - b.z, a.w - b.w);
        }
        sAT[c4+0][rr] = av.x; sAT[c4+1][rr] = av.y;
        sAT[c4+2][rr] = av.z; sAT[c4+3][rr] = av.w;
    }
    for (int kk = r; kk < 64; kk += 16)
        *(float4*)&sB[kk][c4] = *(const float4*)(g_B1 + kk*192 + cb + c4);
    __syncthreads();
    int tx = t & 15, ty = t >> 4;
    int r0 = ty * 4, c0 = tx * 4;
    float acc[4][4] = {};
    #pragma unroll 8
    for (int k = 0; k < 64; k++) {
        float4 av = *(const float4*)&sAT[k][r0];
        float4 bv = *(const float4*)&sB[k][c0];
        float a[4] = {av.x, av.y, av.z, av.w};
        float b[4] = {bv.x, bv.y, bv.z, bv.w};
        #pragma unroll
        for (int ii = 0; ii < 4; ii++)
            #pragma unroll
            for (int jj = 0; jj < 4; jj++)
                acc[ii][jj] = fmaf(a[ii], b[jj], acc[ii][jj]);
    }
    #pragma unroll
    for (int ii = 0; ii < 4; ii++) {
        int node = snode[r0 + ii];
        if (node < 0) continue;
        float* Cp = g_nodeT + (size_t)node*192 + cb + c0;
        float4 co = *(const float4*)Cp;
        co.x += acc[ii][0]; co.y += acc[ii][1]; co.z += acc[ii][2]; co.w += acc[ii][3];
        *(float4*)Cp = co;
    }
}

__global__ void k_scatter0(const float* __restrict__ H) {
    int w = (blockIdx.x * blockDim.x + threadIdx.x) >> 5;
    int lane = threadIdx.x & 31;
    if (w >= E0N) return;
    int src = g_esrc[w], dst = g_edst[w];
    float t = g_logit[w] / g_segsum0[src];
    const float* Hd = g_has[dst] ? (const float*)g_H1 : H;
    float2 hv = ((const float2*)(Hd + (size_t)dst*64))[lane];
    atomicAdd(&g_H2[(size_t)src*64 + 2*lane + 0], t * hv.x);
    atomicAdd(&g_H2[(size_t)src*64 + 2*lane + 1], t * hv.y);
}

// final: out = leaky(Hv @ BL + b); per-row A select has0?H2:(has?H1:H)
__global__ void k_gemmF(const float* __restrict__ H, float* __restrict__ C,
                        const float* __restrict__ bias) {
    __shared__ float sAT[64][72];
    __shared__ float sB[64][72];
    int t = threadIdx.x;
    int rb = blockIdx.x * 64;
    int r = t >> 4, c4 = (t & 15) * 4;
    for (int rr = r; rr < 64; rr += 8) {
        int node = rb + rr;
        const float* Ap = g_has0[node] ? (const float*)g_H2
                         : (g_has[node] ? (const float*)g_H1 : H);
        float4 av = *(const float4*)(Ap + (size_t)node*64 + c4);
        sAT[c4+0][rr] = av.x; sAT[c4+1][rr] = av.y;
        sAT[c4+2][rr] = av.z; sAT[c4+3][rr] = av.w;
    }
    for (int kk = r; kk < 64; kk += 8)
        *(float4*)&sB[kk][c4] = *(const float4*)(g_BL + kk*64 + c4);
    __syncthreads();
    int tx = t & 15, ty = t >> 4;
    int r0 = ty * 8, c0 = tx * 4;
    float acc[8][4] = {};
    #pragma unroll 8
    for (int k = 0; k < 64; k++) {
        float4 a0 = *(const float4*)&sAT[k][r0];
        float4 a1 = *(const float4*)&sAT[k][r0+4];
        float4 bv = *(const float4*)&sB[k][c0];
        float a[8] = {a0.x, a0.y, a0.z, a0.w, a1.x, a1.y, a1.z, a1.w};
        float b[4] = {bv.x, bv.y, bv.z, bv.w};
        #pragma unroll
        for (int ii = 0; ii < 8; ii++)
            #pragma unroll
            for (int jj = 0; jj < 4; jj++)
                acc[ii][jj] = fmaf(a[ii], b[jj], acc[ii][jj]);
    }
    #pragma unroll
    for (int ii = 0; ii < 8; ii++) {
        float4 o = make_float4(acc[ii][0], acc[ii][1], acc[ii][2], acc[ii][3]);
        o.x += bias[c0 + 0]; o.y += bias[c0 + 1];
        o.z += bias[c0 + 2]; o.w += bias[c0 + 3];
        o.x = o.x >= 0.f ? o.x : 0.01f * o.x;
        o.y = o.y >= 0.f ? o.y : 0.01f * o.y;
        o.z = o.z >= 0.f ? o.z : 0.01f * o.z;
        o.w = o.w >= 0.f ? o.w : 0.01f * o.w;
        *(float4*)(C + (size_t)(rb + r0 + ii)*64 + c0) = o;
    }
}

// ---------------- launch ----------------
extern "C" void kernel_launch(void* const* d_in, const int* in_sizes, int n_in,
                              void* d_out, int out_size) {
    const float* score = (const float*)d_in[0];
    const float* H     = (const float*)d_in[1];
    const float* rel0  = (const float*)d_in[2];
    const float* rel1  = (const float*)d_in[3];
    const float* prior = (const float*)d_in[4];
    const float* qst   = (const float*)d_in[5];
    const float* qrl   = (const float*)d_in[6];
    const float* Wlin  = (const float*)d_in[9];
    const float* blin  = (const float*)d_in[10];
    const float* gamma = (const float*)d_in[11];
    const float* Wq    = (const float*)d_in[7];
    const float* Wk    = (const float*)d_in[8];
    const int*   e0    = (const int*)d_in[12];
    const int*   e1    = (const int*)d_in[13];
    float* out = (float*)d_out;

    const int USMEM = (64*68 + 64*196) * 4;   // 67584 B
    cudaFuncSetAttribute(k_uberB, cudaFuncAttributeMaxDynamicSharedMemorySize, USMEM);

    k_prep<<<NBI + 32, 256>>>(out, Wq, Wk);
    k_buildB<<<(64*192 + 2*64*64 + 128*320 + 255)/256, 256>>>(Wlin);
    k_uberB<<<NB_N + NB_QT + NB_QD, 256, USMEM>>>(H, rel1, rel0, qst, qrl);

    // ---- stage 1 ----
    k_logits1<<<E1N/8, 256>>>(e1, rel1, H, prior, gamma);
    k_pass2<<<E1N/256, 256>>>(0, E1N);
    k_topk<<<NQ/8, 256>>>(e1, score, out);
    k_scatter1<<<(NQ*KSEL)/8, 256>>>(H);

    // ---- stage 0 ----
    k_dgemm<<<dim3((NQ*KSEL)/64, 3), 256>>>(H);
    k_logits0<<<E0N/8, 256>>>(e0, rel0, H, E0N);
    k_pass2<<<E0N/256, 256>>>(1, E0N);
    k_scatter0<<<E0N/8, 256>>>(H);

    // ---- final ----
    k_gemmF<<<N_NODES/64, 128>>>(H, out + OFF_REPR, blin);
}

// round 7
// speedup vs baseline: 1.2037x; 1.0104x over previous
#include <cuda_runtime.h>
#include <cstdint>

#define N_NODES 200000
#define DIM 64
#define NQ 4096
#define E1N 262144
#define E0N 131072
#define KSEL 10

#define OFF_REPR  (N_NODES)
#define OFF_PE    (N_NODES + N_NODES*DIM)
#define OFF_OI    (OFF_PE + NQ*KSEL*8)

#define NBI   ((N_NODES + 255)/256)
#define NB_N  (N_NODES/64)
#define NB_QT ((NQ/64)*5)
#define NB_QD ((E1N + E0N)/64)

typedef unsigned long long u64;

// packed f32x2 helpers (FFMA2 — ptxas never emits this from C++; PTX only)
__device__ __forceinline__ u64 pk2(float lo, float hi) {
    u64 r; asm("mov.b64 %0, {%1, %2};" : "=l"(r) : "f"(lo), "f"(hi)); return r;
}
__device__ __forceinline__ void fma2(u64& d, u64 a, u64 b) {
    asm("fma.rn.f32x2 %0, %1, %2, %0;" : "+l"(d) : "l"(a), "l"(b));
}
__device__ __forceinline__ float2 upk(u64 v) {
    float2 r; asm("mov.b64 {%0, %1}, %2;" : "=f"(r.x), "=f"(r.y) : "l"(v)); return r;
}

// ---------------- scratch ----------------
__device__ float    g_M [256*256];
__device__ float    g_B1[64*192];
__device__ float    g_B2[64*64];
__device__ float    g_BL[64*64];
__device__ float    g_Bq[128*320];
__device__ float    g_QT[(size_t)NQ*320];
__device__ float    g_Qk0[NQ];
__device__ float    g_nodeT[(size_t)N_NODES*192];
__device__ float    g_quad1[E1N];
__device__ float    g_quad0[E0N];
__device__ float    g_logit[E1N];
__device__ int      g_esrc[E1N];
__device__ int      g_edst[E1N];
__device__ unsigned g_segmax [N_NODES];
__device__ float    g_segsum [N_NODES];
__device__ unsigned g_segmax0[N_NODES];
__device__ float    g_segsum0[N_NODES];
__device__ int      g_has [N_NODES];
__device__ int      g_has0[N_NODES];
__device__ float    g_H1[(size_t)N_NODES*DIM];
__device__ float    g_H2[(size_t)N_NODES*DIM];
__device__ int      g_psrc[NQ*KSEL];
__device__ int      g_pdst[NQ*KSEL];
__device__ float    g_ptrans[NQ*KSEL];
__device__ int      g_chg[NQ*KSEL];
__device__ int      g_ncnt;

__device__ __forceinline__ unsigned encf(float f) {
    unsigned u = __float_as_uint(f);
    return (u & 0x80000000u) ? ~u : (u | 0x80000000u);
}
__device__ __forceinline__ float decf(unsigned u) {
    return (u & 0x80000000u) ? __uint_as_float(u & 0x7fffffffu) : __uint_as_float(~u);
}

// ---------------- launch A: init ∥ M = Wq^T @ Wk ----------------
__global__ void k_prep(float* __restrict__ outScore,
                       const float* __restrict__ Wq, const float* __restrict__ Wk) {
    __shared__ float sA[64][36];
    __shared__ float sB[64][72];
    int t = threadIdx.x;
    if (blockIdx.x < NBI) {
        int i = blockIdx.x * 256 + t;
        if (i < N_NODES) {
            g_segmax[i] = 0u;  g_segsum[i] = 0.f;
            g_segmax0[i] = 0u; g_segsum0[i] = 0.f;
            g_has[i] = 0; g_has0[i] = 0;
            outScore[i] = 0.f;
        }
        if (i < NQ) g_Qk0[i] = 0.f;
        if (i == 0) g_ncnt = 0;
        return;
    }
    int b = blockIdx.x - NBI;
    int ib = (b & 7) * 32, jb = (b >> 3) * 64;
    int tx = t & 15, ty = t >> 4;
    int r0 = ty * 2, c0 = tx * 4;
    float acc[2][4] = {};
    for (int kc = 0; kc < 256; kc += 64) {
        __syncthreads();
        {
            int ra = t >> 3, ca = (t & 7) * 4;
            for (int kk = ra; kk < 64; kk += 32)
                *(float4*)&sA[kk][ca] = *(const float4*)(Wq + (size_t)(kc + kk)*256 + ib + ca);
            int rbb = t >> 4, cbb = (t & 15) * 4;
            for (int kk = rbb; kk < 64; kk += 16)
                *(float4*)&sB[kk][cbb] = *(const float4*)(Wk + (size_t)(kc + kk)*256 + jb + cbb);
        }
        __syncthreads();
        #pragma unroll 8
        for (int k = 0; k < 64; k++) {
            float2 av = *(const float2*)&sA[k][r0];
            float4 bv = *(const float4*)&sB[k][c0];
            float a[2] = {av.x, av.y};
            float bb[4] = {bv.x, bv.y, bv.z, bv.w};
            #pragma unroll
            for (int ii = 0; ii < 2; ii++)
                #pragma unroll
                for (int jj = 0; jj < 4; jj++)
                    acc[ii][jj] = fmaf(a[ii], bb[jj], acc[ii][jj]);
        }
    }
    #pragma unroll
    for (int ii = 0; ii < 2; ii++)
        *(float4*)(g_M + (size_t)(ib + r0 + ii)*256 + jb + c0) =
            make_float4(acc[ii][0], acc[ii][1], acc[ii][2], acc[ii][3]);
}

__global__ void k_buildB(const float* __restrict__ W_lin) {
    int t = blockIdx.x * blockDim.x + threadIdx.x;
    if (t < 64*192) {
        int k = t / 192, c = t % 192;
        float v;
        if (c < 128) v = g_M[k*256 + c];
        else         v = g_M[(64 + (c-128))*256 + k];
        g_B1[t] = v;
    } else if (t < 64*192 + 64*64) {
        int t2 = t - 64*192; int k = t2 / 64, i = t2 % 64;
        g_B2[t2] = g_M[(64+i)*256 + (64+k)];
    } else if (t < 64*192 + 2*64*64) {
        int t3 = t - 64*192 - 64*64; int k = t3 / 64, i = t3 % 64;
        g_BL[t3] = W_lin[i*64 + k];
    } else if (t < 64*192 + 2*64*64 + 128*320) {
        int t4 = t - 64*192 - 2*64*64;
        int k = t4 / 320, c = t4 % 320;
        float v;
        if      (c < 64)  v = g_M[(128+k)*256 + c];
        else if (c < 128) v = g_M[(128+k)*256 + c] + g_M[c*256 + 128 + k];
        else if (c < 192) v = g_M[(c-128)*256 + 128 + k];
        else              v = g_M[(c-64)*256 + 128 + k];
        g_Bq[t4] = v;
    }
}

// ---------------- launch B: gemmN ∥ gemmQ(+k0) ∥ quadBoth (f32x2 packed) ----------------
extern __shared__ float smU[];

__device__ void gemmN_body(int bidN, const float* __restrict__ A) {
    float (*sAT)[68] = (float(*)[68])smU;
    float (*sB)[196] = (float(*)[196])(smU + 64*68);
    int t = threadIdx.x;
    int rb = bidN * 64;
    {
        int r = t >> 4, c4 = (t & 15) * 4;
        for (int rr = r; rr < 64; rr += 16) {
            float4 av = *(const float4*)(A + (size_t)(rb + rr)*64 + c4);
            sAT[c4+0][rr] = av.x; sAT[c4+1][rr] = av.y;
            sAT[c4+2][rr] = av.z; sAT[c4+3][rr] = av.w;
        }
        for (int kk = r; kk < 64; kk += 16) {
            #pragma unroll
            for (int co = 0; co < 3; co++)
                *(float4*)&sB[kk][c4 + co*64] = *(const float4*)(g_B1 + (size_t)kk*192 + c4 + co*64);
        }
    }
    __syncthreads();
    int tx = t & 15, ty = t >> 4;
    int r0 = ty * 4, c0 = tx * 4;
    u64 acc2[4][6] = {};
    #pragma unroll 4
    for (int k = 0; k < 64; k++) {
        float4 av = *(const float4*)&sAT[k][r0];
        u64 a2[4] = {pk2(av.x, av.x), pk2(av.y, av.y), pk2(av.z, av.z), pk2(av.w, av.w)};
        u64 b2[6];
        #pragma unroll
        for (int co = 0; co < 3; co++) {
            b2[co*2+0] = *(const u64*)&sB[k][c0 + co*64];
            b2[co*2+1] = *(const u64*)&sB[k][c0 + co*64 + 2];
        }
        #pragma unroll
        for (int ii = 0; ii < 4; ii++)
            #pragma unroll
            for (int jj = 0; jj < 6; jj++)
                fma2(acc2[ii][jj], a2[ii], b2[jj]);
    }
    #pragma unroll
    for (int ii = 0; ii < 4; ii++) {
        float* Cp = g_nodeT + (size_t)(rb + r0 + ii)*192;
        #pragma unroll
        for (int co = 0; co < 3; co++) {
            *(u64*)(Cp + c0 + co*64)     = acc2[ii][co*2+0];
            *(u64*)(Cp + c0 + co*64 + 2) = acc2[ii][co*2+1];
        }
    }
}

__device__ void gemmQ_body(int b, const float* __restrict__ qst, const float* __restrict__ qrl) {
    float (*sAT)[72] = (float(*)[72])smU;
    float (*sB)[72]  = (float(*)[72])(smU + 64*72);
    int t = threadIdx.x;
    int rb = (b & 63) * 64, cb = (b >> 6) * 64;
    int tx = t & 15, ty = t >> 4;
    int r0 = ty * 4, c0 = tx * 4;
    u64 acc2[4][2] = {};
    for (int kc = 0; kc < 128; kc += 64) {
        __syncthreads();
        {
            const float* Qsrc = (kc == 0) ? qst : qrl;
            int r = t >> 4, c4 = (t & 15) * 4;
            for (int rr = r; rr < 64; rr += 16) {
                float4 av = *(const float4*)(Qsrc + (size_t)(rb + rr)*64 + c4);
                sAT[c4+0][rr] = av.x; sAT[c4+1][rr] = av.y;
                sAT[c4+2][rr] = av.z; sAT[c4+3][rr] = av.w;
            }
            for (int kk = r; kk < 64; kk += 16)
                *(float4*)&sB[kk][c4] = *(const float4*)(g_Bq + (size_t)(kc + kk)*320 + cb + c4);
        }
        __syncthreads();
        #pragma unroll 8
        for (int k = 0; k < 64; k++) {
            float4 av = *(const float4*)&sAT[k][r0];
            u64 a2[4] = {pk2(av.x, av.x), pk2(av.y, av.y), pk2(av.z, av.z), pk2(av.w, av.w)};
            u64 b0 = *(const u64*)&sB[k][c0];
            u64 b1 = *(const u64*)&sB[k][c0 + 2];
            #pragma unroll
            for (int ii = 0; ii < 4; ii++) {
                fma2(acc2[ii][0], a2[ii], b0);
                fma2(acc2[ii][1], a2[ii], b1);
            }
        }
    }
    if (cb < 192) {
        #pragma unroll
        for (int ii = 0; ii < 4; ii++) {
            float* Cp = g_QT + (size_t)(rb + r0 + ii)*320 + cb + c0;
            *(u64*)Cp       = acc2[ii][0];
            *(u64*)(Cp + 2) = acc2[ii][1];
        }
    } else {
        const float* Qsrc2 = (cb == 192) ? qst : qrl;
        float qp[4];
        #pragma unroll
        for (int ii = 0; ii < 4; ii++) {
            float4 a = *(const float4*)(Qsrc2 + (size_t)(rb + r0 + ii)*64 + c0);
            float2 p0 = upk(acc2[ii][0]), p1 = upk(acc2[ii][1]);
            qp[ii] = p0.x*a.x + p0.y*a.y + p1.x*a.z + p1.y*a.w;
        }
        #pragma unroll
        for (int off = 8; off; off >>= 1)
            #pragma unroll
            for (int ii = 0; ii < 4; ii++)
                qp[ii] += __shfl_down_sync(~0u, qp[ii], off, 16);
        if (tx == 0) {
            #pragma unroll
            for (int ii = 0; ii < 4; ii++)
                atomicAdd(&g_Qk0[rb + r0 + ii], qp[ii]);
        }
    }
}

__device__ void quad_body(int b, const float* __restrict__ rel1, const float* __restrict__ rel0) {
    const float* rel; float* quadOut; int rb;
    if (b < E1N/64) { rel = rel1; quadOut = g_quad1; rb = b * 64; }
    else            { rel = rel0; quadOut = g_quad0; rb = (b - E1N/64) * 64; }
    float (*sAT)[72] = (float(*)[72])smU;
    float (*sB)[72]  = (float(*)[72])(smU + 64*72);
    int t = threadIdx.x;
    int r = t >> 4, c4 = (t & 15) * 4;
    for (int rr = r; rr < 64; rr += 16) {
        float4 av = *(const float4*)(rel + (size_t)(rb + rr)*64 + c4);
        sAT[c4+0][rr] = av.x; sAT[c4+1][rr] = av.y;
        sAT[c4+2][rr] = av.z; sAT[c4+3][rr] = av.w;
    }
    for (int kk = r; kk < 64; kk += 16)
        *(float4*)&sB[kk][c4] = *(const float4*)(g_B2 + kk*64 + c4);
    __syncthreads();
    int tx = t & 15, ty = t >> 4;
    int r0 = ty * 4, c0 = tx * 4;
    u64 acc2[4][2] = {};
    #pragma unroll 8
    for (int k = 0; k < 64; k++) {
        float4 av = *(const float4*)&sAT[k][r0];
        u64 a2[4] = {pk2(av.x, av.x), pk2(av.y, av.y), pk2(av.z, av.z), pk2(av.w, av.w)};
        u64 b0 = *(const u64*)&sB[k][c0];
        u64 b1 = *(const u64*)&sB[k][c0 + 2];
        #pragma unroll
        for (int ii = 0; ii < 4; ii++) {
            fma2(acc2[ii][0], a2[ii], b0);
            fma2(acc2[ii][1], a2[ii], b1);
        }
    }
    float qp[4];
    #pragma unroll
    for (int ii = 0; ii < 4; ii++) {
        float4 a = *(const float4*)(rel + (size_t)(rb + r0 + ii)*64 + c0);
        float2 p0 = upk(acc2[ii][0]), p1 = upk(acc2[ii][1]);
        qp[ii] = p0.x*a.x + p0.y*a.y + p1.x*a.z + p1.y*a.w;
    }
    #pragma unroll
    for (int off = 8; off; off >>= 1)
        #pragma unroll
        for (int ii = 0; ii < 4; ii++)
            qp[ii] += __shfl_down_sync(~0u, qp[ii], off, 16);
    if (tx == 0) {
        #pragma unroll
        for (int ii = 0; ii < 4; ii++) quadOut[rb + r0 + ii] = qp[ii];
    }
}

__global__ void k_uberB(const float* __restrict__ H,
                        const float* __restrict__ rel1, const float* __restrict__ rel0,
                        const float* __restrict__ qst,  const float* __restrict__ qrl) {
    int bid = blockIdx.x;
    if (bid < NB_N)              gemmN_body(bid, H);
    else if (bid < NB_N + NB_QT) gemmQ_body(bid - NB_N, qst, qrl);
    else                         quad_body(bid - NB_N - NB_QT, rel1, rel0);
}

// ---------------- logits ----------------
__global__ void k_logits1(const int* __restrict__ edges, const float* __restrict__ rel,
                          const float* __restrict__ H, const float* __restrict__ prior,
                          const float* __restrict__ gammaPtr) {
    __shared__ float sQ[192];
    __shared__ float sk0;
    int t = threadIdx.x;
    int q = blockIdx.x >> 3;
    if (t < 192) sQ[t] = g_QT[(size_t)q*320 + t];
    if (t == 192) sk0 = g_Qk0[q];
    __syncthreads();
    int w = blockIdx.x * 8 + (t >> 5);
    int lane = t & 31;
    int src = edges[w*8 + 6], dst = edges[w*8 + 7];
    const float2* hs  = (const float2*)(H + (size_t)src*64);
    const float2* hd  = (const float2*)(H + (size_t)dst*64);
    const float2* nts = (const float2*)(g_nodeT + (size_t)src*192);
    const float2* ntd = (const float2*)(g_nodeT + (size_t)dst*192);
    const float2* rp  = (const float2*)(rel + (size_t)w*64);
    float2 P  = nts[lane];
    float2 U  = nts[32 + lane];
    float2 Wd = ntd[64 + lane];
    float2 hdv = hd[lane], hsv = hs[lane], rv = rp[lane];
    float2 dq = ((const float2*)sQ)[lane];
    float2 cq = ((const float2*)(sQ + 64))[lane];
    float2 vq = ((const float2*)(sQ + 128))[lane];
    float acc = (P.x + dq.x) * hdv.x + (P.y + dq.y) * hdv.y;
    acc = fmaf(rv.x, (U.x + cq.x + Wd.x), acc);
    acc = fmaf(rv.y, (U.y + cq.y + Wd.y), acc);
    acc = fmaf(vq.x, hsv.x, acc);
    acc = fmaf(vq.y, hsv.y, acc);
    for (int o = 16; o; o >>= 1) acc += __shfl_xor_sync(~0u, acc, o);
    if (lane == 0) {
        float l = acc + sk0 + g_quad1[w];
        l = fmaf(gammaPtr[0], prior[w], l);
        g_logit[w] = l;
        g_esrc[w] = src; g_edst[w] = dst;
        atomicMax(&g_segmax[src], encf(l));
    }
}

__global__ void k_logits0(const int* __restrict__ edges, const float* __restrict__ rel,
                          const float* __restrict__ H, int nE) {
    int w = (blockIdx.x * blockDim.x + threadIdx.x) >> 5;
    int lane = threadIdx.x & 31;
    if (w >= nE) return;
    int q = edges[w*8 + 0], src = edges[w*8 + 6], dst = edges[w*8 + 7];
    const float* Hs = g_has[src] ? (const float*)g_H1 : H;
    const float* Hd = g_has[dst] ? (const float*)g_H1 : H;
    const float2* hs  = (const float2*)(Hs + (size_t)src*64);
    const float2* hd  = (const float2*)(Hd + (size_t)dst*64);
    const float2* nts = (const float2*)(g_nodeT + (size_t)src*192);
    const float2* ntd = (const float2*)(g_nodeT + (size_t)dst*192);
    const float2* rp  = (const float2*)(rel + (size_t)w*64);
    const float2* qd  = (const float2*)(g_QT + (size_t)q*320);
    const float2* qc  = (const float2*)(g_QT + (size_t)q*320 + 64);
    const float2* qv  = (const float2*)(g_QT + (size_t)q*320 + 128);
    float2 P  = nts[lane];
    float2 U  = nts[32 + lane];
    float2 Wd = ntd[64 + lane];
    float2 hdv = hd[lane], hsv = hs[lane], rv = rp[lane];
    float2 dq = qd[lane], cq = qc[lane], vq = qv[lane];
    float acc = (P.x + dq.x) * hdv.x + (P.y + dq.y) * hdv.y;
    acc = fmaf(rv.x, (U.x + cq.x + Wd.x), acc);
    acc = fmaf(rv.y, (U.y + cq.y + Wd.y), acc);
    acc = fmaf(vq.x, hsv.x, acc);
    acc = fmaf(vq.y, hsv.y, acc);
    for (int o = 16; o; o >>= 1) acc += __shfl_xor_sync(~0u, acc, o);
    if (lane == 0) {
        float l = acc + g_Qk0[q] + g_quad0[w];
        g_logit[w] = l;
        g_esrc[w] = src; g_edst[w] = dst;
        atomicMax(&g_segmax0[src], encf(l));
    }
}

__global__ void k_pass2(int stage0, int nE) {
    int e = blockIdx.x * blockDim.x + threadIdx.x;
    if (e >= nE) return;
    int src = g_esrc[e];
    if (!stage0) {
        float mx = decf(g_segmax[src]);
        float v = expf(g_logit[e] - mx);
        g_logit[e] = v;
        atomicAdd(&g_segsum[src], v);
    } else {
        float mx = decf(g_segmax0[src]);
        float v = expf(g_logit[e] - mx);
        g_logit[e] = v;
        atomicAdd(&g_segsum0[src], v);
        if (atomicExch(&g_has0[src], 1) == 0) {
            float4* hp = (float4*)(g_H2 + (size_t)src*64);
            #pragma unroll
            for (int c = 0; c < 16; c++) hp[c] = make_float4(0.f, 0.f, 0.f, 0.f);
        }
    }
}

__global__ void k_topk(const int* __restrict__ edges1, const float* __restrict__ score,
                       float* __restrict__ out) {
    int w = (blockIdx.x * blockDim.x + threadIdx.x) >> 5;
    int lane = threadIdx.x & 31;
    if (w >= NQ) return;
    int g0 = lane, g1 = lane + 32;
    int e0 = w*64 + g0, e1 = w*64 + g1;
    int s0 = g_esrc[e0], s1 = g_esrc[e1];
    float tr0 = g_logit[e0] / g_segsum[s0];
    float tr1 = g_logit[e1] / g_segsum[s1];
    float v0 = tr0 * score[s0];
    float v1 = tr1 * score[s1];
    int myG = 0; float myTr = 0.f;
    for (int k = 0; k < KSEL; k++) {
        float bv; int bg; float bt;
        if (v0 >= v1) { bv = v0; bg = g0; bt = tr0; }
        else          { bv = v1; bg = g1; bt = tr1; }
        for (int o = 16; o; o >>= 1) {
            float ov = __shfl_xor_sync(~0u, bv, o);
            int   og = __shfl_xor_sync(~0u, bg, o);
            float ot = __shfl_xor_sync(~0u, bt, o);
            if (ov > bv || (ov == bv && og < bg)) { bv = ov; bg = og; bt = ot; }
        }
        if (lane == k) { myG = bg; myTr = bt; }
        if (g0 == bg) v0 = -__int_as_float(0x7f800000);
        if (g1 == bg) v1 = -__int_as_float(0x7f800000);
    }
    if (lane < KSEL) {
        int orig = w*64 + myG;
        int oi = w*KSEL + lane;
        int src = g_esrc[orig], dst = g_edst[orig];
        g_psrc[oi] = src; g_pdst[oi] = dst; g_ptrans[oi] = myTr;
        if (atomicExch(&g_has[src], 1) == 0) {
            int idx = atomicAdd(&g_ncnt, 1);
            g_chg[idx] = src;
            float4* hp = (float4*)(g_H1 + (size_t)src*64);
            #pragma unroll
            for (int c = 0; c < 16; c++) hp[c] = make_float4(0.f, 0.f, 0.f, 0.f);
        }
        atomicAdd(out + dst, myTr * score[src]);
        float* pe = out + OFF_PE + (size_t)oi*8;
        for (int c = 0; c < 8; c++) pe[c] = (float)edges1[orig*8 + c];
        out[OFF_OI + oi] = (float)orig;
    }
}

__global__ void k_scatter1(const float* __restrict__ H) {
    int w = (blockIdx.x * blockDim.x + threadIdx.x) >> 5;
    int lane = threadIdx.x & 31;
    if (w >= NQ*KSEL) return;
    int src = g_psrc[w], dst = g_pdst[w];
    float t = g_ptrans[w];
    float2 hv = ((const float2*)(H + (size_t)dst*64))[lane];
    atomicAdd(&g_H1[(size_t)src*64 + 2*lane + 0], t * hv.x);
    atomicAdd(&g_H1[(size_t)src*64 + 2*lane + 1], t * hv.y);
}

__global__ void k_dgemm(const float* __restrict__ Hold) {
    int cnt = g_ncnt;
    int rb = blockIdx.x * 64;
    if (rb >= cnt) return;
    __shared__ float sAT[64][72];
    __shared__ float sB[64][72];
    __shared__ int snode[64];
    int t = threadIdx.x;
    int cb = blockIdx.y * 64;
    if (t < 64) snode[t] = (rb + t < cnt) ? g_chg[rb + t] : -1;
    __syncthreads();
    int r = t >> 4, c4 = (t & 15) * 4;
    for (int rr = r; rr < 64; rr += 16) {
        int node = snode[rr];
        float4 av = make_float4(0.f, 0.f, 0.f, 0.f);
        if (node >= 0) {
            float4 a = *(const float4*)(g_H1 + (size_t)node*64 + c4);
            float4 b = *(const float4*)(Hold + (size_t)node*64 + c4);
            av = make_float4(a.x - b.x, a.y - b.y, a.z - b.z, a.w - b.w);
        }
        sAT[c4+0][rr] = av.x; sAT[c4+1][rr] = av.y;
        sAT[c4+2][rr] = av.z; sAT[c4+3][rr] = av.w;
    }
    for (int kk = r; kk < 64; kk += 16)
        *(float4*)&sB[kk][c4] = *(const float4*)(g_B1 + kk*192 + cb + c4);
    __syncthreads();
    int tx = t & 15, ty = t >> 4;
    int r0 = ty * 4, c0 = tx * 4;
    float acc[4][4] = {};
    #pragma unroll 8
    for (int k = 0; k < 64; k++) {
        float4 av = *(const float4*)&sAT[k][r0];
        float4 bv = *(const float4*)&sB[k][c0];
        float a[4] = {av.x, av.y, av.z, av.w};
        float b[4] = {bv.x, bv.y, bv.z, bv.w};
        #pragma unroll
        for (int ii = 0; ii < 4; ii++)
            #pragma unroll
            for (int jj = 0; jj < 4; jj++)
                acc[ii][jj] = fmaf(a[ii], b[jj], acc[ii][jj]);
    }
    #pragma unroll
    for (int ii = 0; ii < 4; ii++) {
        int node = snode[r0 + ii];
        if (node < 0) continue;
        float* Cp = g_nodeT + (size_t)node*192 + cb + c0;
        float4 co = *(const float4*)Cp;
        co.x += acc[ii][0]; co.y += acc[ii][1]; co.z += acc[ii][2]; co.w += acc[ii][3];
        *(float4*)Cp = co;
    }
}

__global__ void k_scatter0(const float* __restrict__ H) {
    int w = (blockIdx.x * blockDim.x + threadIdx.x) >> 5;
    int lane = threadIdx.x & 31;
    if (w >= E0N) return;
    int src = g_esrc[w], dst = g_edst[w];
    float t = g_logit[w] / g_segsum0[src];
    const float* Hd = g_has[dst] ? (const float*)g_H1 : H;
    float2 hv = ((const float2*)(Hd + (size_t)dst*64))[lane];
    atomicAdd(&g_H2[(size_t)src*64 + 2*lane + 0], t * hv.x);
    atomicAdd(&g_H2[(size_t)src*64 + 2*lane + 1], t * hv.y);
}

// final GEMM (f32x2, pairs along rows)
__global__ void k_gemmF(const float* __restrict__ H, float* __restrict__ C,
                        const float* __restrict__ bias) {
    __shared__ float sAT[64][72];
    __shared__ float sB[64][72];
    int t = threadIdx.x;
    int rb = blockIdx.x * 64;
    int r = t >> 4, c4 = (t & 15) * 4;
    for (int rr = r; rr < 64; rr += 8) {
        int node = rb + rr;
        const float* Ap = g_has0[node] ? (const float*)g_H2
                         : (g_has[node] ? (const float*)g_H1 : H);
        float4 av = *(const float4*)(Ap + (size_t)node*64 + c4);
        sAT[c4+0][rr] = av.x; sAT[c4+1][rr] = av.y;
        sAT[c4+2][rr] = av.z; sAT[c4+3][rr] = av.w;
    }
    for (int kk = r; kk < 64; kk += 8)
        *(float4*)&sB[kk][c4] = *(const float4*)(g_BL + kk*64 + c4);
    __syncthreads();
    int tx = t & 15, ty = t >> 4;
    int r0 = ty * 8, c0 = tx * 4;
    u64 acc2[4][4] = {};     // acc2[p][jj] = C[(r0+2p, r0+2p+1)][c0+jj]
    #pragma unroll 8
    for (int k = 0; k < 64; k++) {
        u64 a2[4];
        #pragma unroll
        for (int p = 0; p < 4; p++) a2[p] = *(const u64*)&sAT[k][r0 + 2*p];
        float4 bv = *(const float4*)&sB[k][c0];
        u64 b2[4] = {pk2(bv.x, bv.x), pk2(bv.y, bv.y), pk2(bv.z, bv.z), pk2(bv.w, bv.w)};
        #pragma unroll
        for (int p = 0; p < 4; p++)
            #pragma unroll
            for (int jj = 0; jj < 4; jj++)
                fma2(acc2[p][jj], a2[p], b2[jj]);
    }
    #pragma unroll
    for (int p = 0; p < 4; p++) {
        float2 v0 = upk(acc2[p][0]), v1 = upk(acc2[p][1]);
        float2 v2 = upk(acc2[p][2]), v3 = upk(acc2[p][3]);
        float rowv[2][4] = {{v0.x, v1.x, v2.x, v3.x}, {v0.y, v1.y, v2.y, v3.y}};
        #pragma unroll
        for (int s = 0; s < 2; s++) {
            float4 o = make_float4(rowv[s][0], rowv[s][1], rowv[s][2], rowv[s][3]);
            o.x += bias[c0 + 0]; o.y += bias[c0 + 1];
            o.z += bias[c0 + 2]; o.w += bias[c0 + 3];
            o.x = o.x >= 0.f ? o.x : 0.01f * o.x;
            o.y = o.y >= 0.f ? o.y : 0.01f * o.y;
            o.z = o.z >= 0.f ? o.z : 0.01f * o.z;
            o.w = o.w >= 0.f ? o.w : 0.01f * o.w;
            *(float4*)(C + (size_t)(rb + r0 + 2*p + s)*64 + c0) = o;
        }
    }
}

// ---------------- launch ----------------
extern "C" void kernel_launch(void* const* d_in, const int* in_sizes, int n_in,
                              void* d_out, int out_size) {
    const float* score = (const float*)d_in[0];
    const float* H     = (const float*)d_in[1];
    const float* rel0  = (const float*)d_in[2];
    const float* rel1  = (const float*)d_in[3];
    const float* prior = (const float*)d_in[4];
    const float* qst   = (const float*)d_in[5];
    const float* qrl   = (const float*)d_in[6];
    const float* Wq    = (const float*)d_in[7];
    const float* Wk    = (const float*)d_in[8];
    const float* Wlin  = (const float*)d_in[9];
    const float* blin  = (const float*)d_in[10];
    const float* gamma = (const float*)d_in[11];
    const int*   e0    = (const int*)d_in[12];
    const int*   e1    = (const int*)d_in[13];
    float* out = (float*)d_out;

    const int USMEM = (64*68 + 64*196) * 4;   // 67584 B
    cudaFuncSetAttribute(k_uberB, cudaFuncAttributeMaxDynamicSharedMemorySize, USMEM);

    k_prep<<<NBI + 32, 256>>>(out, Wq, Wk);
    k_buildB<<<(64*192 + 2*64*64 + 128*320 + 255)/256, 256>>>(Wlin);
    k_uberB<<<NB_N + NB_QT + NB_QD, 256, USMEM>>>(H, rel1, rel0, qst, qrl);

    // ---- stage 1 ----
    k_logits1<<<E1N/8, 256>>>(e1, rel1, H, prior, gamma);
    k_pass2<<<E1N/256, 256>>>(0, E1N);
    k_topk<<<NQ/8, 256>>>(e1, score, out);
    k_scatter1<<<(NQ*KSEL)/8, 256>>>(H);

    // ---- stage 0 ----
    k_dgemm<<<dim3((NQ*KSEL)/64, 3), 256>>>(H);
    k_logits0<<<E0N/8, 256>>>(e0, rel0, H, E0N);
    k_pass2<<<E0N/256, 256>>>(1, E0N);
    k_scatter0<<<E0N/8, 256>>>(H);

    // ---- final ----
    k_gemmF<<<N_NODES/64, 128>>>(H, out + OFF_REPR, blin);
}